// round 5
// baseline (speedup 1.0000x reference)
#include <cuda_runtime.h>
#include <cuda_bf16.h>
#include <math.h>

// Problem constants: B=2, S=2048, D=2048, H=16, Dh=128
#define BB 2
#define SS 2048
#define DD 2048
#define HH 16
#define DH 128
#define MM (BB*SS)          // 4096 rows for the projection GEMMs

// ---------------------------------------------------------------------------
// Scratch (device globals — allocation-free per harness rules)
// ---------------------------------------------------------------------------
__device__ float g_Q[BB*SS*DD];    // Q projection, [B*S, D] row-major
__device__ float g_ctx[BB*SS*DD];  // attention context, [B*S, D] row-major

// ---------------------------------------------------------------------------
// GEMM: C[M,N] = A[M,K] @ W[K,N] + bias[N]
// M=4096, N=2048, K=2048. 128x128 block tile, BK=8, 256 threads, 8x8/thread.
// mode 0: C row-major.  mode 1: head-transposed store into [B,H,S,Dh].
// ---------------------------------------------------------------------------
#define GBM 128
#define GBN 128
#define GBK 8

__global__ __launch_bounds__(256, 2)
void mhsa_gemm_kernel(const float* __restrict__ A, const float* __restrict__ W,
                      const float* __restrict__ bias, float* __restrict__ C,
                      int mode)
{
    const int N = DD, K = DD;
    __shared__ float As[GBK][GBM];   // A stored transposed: As[k][m]
    __shared__ float Bs[GBK][GBN];

    const int tid = threadIdx.x;
    const int bm = blockIdx.y * GBM;
    const int bn = blockIdx.x * GBN;
    const int tx = tid & 15;
    const int ty = tid >> 4;

    // A tile load mapping: one float4 per thread
    const int arow = tid >> 1;
    const int acol = (tid & 1) * 4;
    // B tile load mapping
    const int brow = tid >> 5;
    const int bcol = (tid & 31) * 4;

    float acc[8][8];
#pragma unroll
    for (int i = 0; i < 8; i++)
#pragma unroll
        for (int j = 0; j < 8; j++) acc[i][j] = 0.f;

    const float* Aptr = A + (size_t)(bm + arow) * K + acol;
    const float* Wptr = W + (size_t)brow * N + (bn + bcol);

    for (int k0 = 0; k0 < K; k0 += GBK) {
        float4 av = *(const float4*)Aptr;
        As[acol + 0][arow] = av.x;
        As[acol + 1][arow] = av.y;
        As[acol + 2][arow] = av.z;
        As[acol + 3][arow] = av.w;
        *(float4*)&Bs[brow][bcol] = *(const float4*)Wptr;
        __syncthreads();

#pragma unroll
        for (int kk = 0; kk < GBK; kk++) {
            float a[8], b[8];
            *(float4*)&a[0] = *(const float4*)&As[kk][ty * 4];
            *(float4*)&a[4] = *(const float4*)&As[kk][64 + ty * 4];
            *(float4*)&b[0] = *(const float4*)&Bs[kk][tx * 4];
            *(float4*)&b[4] = *(const float4*)&Bs[kk][64 + tx * 4];
#pragma unroll
            for (int i = 0; i < 8; i++)
#pragma unroll
                for (int j = 0; j < 8; j++)
                    acc[i][j] = fmaf(a[i], b[j], acc[i][j]);
        }
        __syncthreads();
        Aptr += GBK;
        Wptr += (size_t)GBK * N;
    }

    // Epilogue
#pragma unroll
    for (int i = 0; i < 8; i++) {
        int ri = (i < 4) ? (ty * 4 + i) : (64 + ty * 4 + (i - 4));
        int row = bm + ri;
#pragma unroll
        for (int j = 0; j < 8; j++) {
            int cj = (j < 4) ? (tx * 4 + j) : (64 + tx * 4 + (j - 4));
            int col = bn + cj;
            float v = acc[i][j] + bias[col];
            if (mode == 0) {
                C[(size_t)row * N + col] = v;
            } else {
                int b_ = row >> 11;        // / S
                int s_ = row & (SS - 1);
                int h_ = col >> 7;         // / Dh
                int d_ = col & (DH - 1);
                C[(size_t)(((b_ * HH + h_) * SS) + s_) * DH + d_] = v;
            }
        }
    }
}

// ---------------------------------------------------------------------------
// Causal flash attention. One CTA per (qblock, h, b).
// BQ=64 queries, BKV=64 keys per iteration, Dh=128, fp32.
// 256 threads: tx=tid&15, ty=tid>>4. S tile: 4x4/thread. ctx: 4 rows x 8 cols.
// Smem (dynamic, 114944 B): Qst[128][64], Kst[128][64] (d-major), Vs[64][128],
// Pt[64][65] (P transposed, padded).
// ---------------------------------------------------------------------------
#define BQ 64
#define BKV 64
#define ATT_SMEM_FLOATS (8192 + 8192 + 8192 + 64*65)
#define ATT_SMEM_BYTES  (ATT_SMEM_FLOATS * 4)

__global__ __launch_bounds__(256, 1)
void mhsa_attn_kernel(const float* __restrict__ Q, const float* __restrict__ K,
                      const float* __restrict__ V, float* __restrict__ ctxout)
{
    extern __shared__ float sm[];
    float* Qst = sm;              // [128][64]  Qst[d*64 + q]
    float* Kst = sm + 8192;       // [128][64]
    float* Vs  = sm + 16384;      // [64][128]
    float* Pt  = sm + 24576;      // [64][65]   Pt[k*65 + q]

    const int qb = blockIdx.x;
    const int h  = blockIdx.y;
    const int b  = blockIdx.z;
    const int tid = threadIdx.x;
    const int tx = tid & 15;
    const int ty = tid >> 4;
    const int lq  = tid & 31;          // q/k index for transposed loads (warp-spread)
    const int ld4 = (tid >> 5) * 4;    // d base

    // ---- Load Q tile transposed: Qst[d][q] ----
    const float* Qbase = Q + (size_t)(b * SS + qb * BQ) * DD + h * DH;
#pragma unroll
    for (int qh = 0; qh < 2; qh++)
#pragma unroll
        for (int dh = 0; dh < 4; dh++) {
            int q = qh * 32 + lq;
            int d = dh * 32 + ld4;
            float4 v = *(const float4*)(Qbase + (size_t)q * DD + d);
            Qst[(d + 0) * 64 + q] = v.x;
            Qst[(d + 1) * 64 + q] = v.y;
            Qst[(d + 2) * 64 + q] = v.z;
            Qst[(d + 3) * 64 + q] = v.w;
        }

    float ctx[4][8];
    float m[4], l[4];
#pragma unroll
    for (int i = 0; i < 4; i++) {
        m[i] = -INFINITY; l[i] = 0.f;
#pragma unroll
        for (int j = 0; j < 8; j++) ctx[i][j] = 0.f;
    }

    const float scale = 0.08838834764831845f;  // 1/sqrt(128)
    const float* Kbh = K + (size_t)((b * HH + h) * SS) * DH;
    const float* Vbh = V + (size_t)((b * HH + h) * SS) * DH;

    for (int kb = 0; kb <= qb; kb++) {
        __syncthreads();   // previous iteration's PV reads done before overwrite
        const float* Kb = Kbh + (size_t)kb * BKV * DH;
        const float* Vb = Vbh + (size_t)kb * BKV * DH;
        // K transposed load: Kst[d][k]
#pragma unroll
        for (int qh = 0; qh < 2; qh++)
#pragma unroll
            for (int dh = 0; dh < 4; dh++) {
                int k = qh * 32 + lq;
                int d = dh * 32 + ld4;
                float4 v = *(const float4*)(Kb + (size_t)k * DH + d);
                Kst[(d + 0) * 64 + k] = v.x;
                Kst[(d + 1) * 64 + k] = v.y;
                Kst[(d + 2) * 64 + k] = v.z;
                Kst[(d + 3) * 64 + k] = v.w;
            }
        // V row-major load (coalesced)
#pragma unroll
        for (int it = 0; it < 8; it++) {
            int idx = it * 256 + tid;
            ((float4*)Vs)[idx] = ((const float4*)Vb)[idx];
        }
        __syncthreads();

        // ---- S = Q K^T (4x4 per thread) ----
        float s4[4][4];
#pragma unroll
        for (int i = 0; i < 4; i++)
#pragma unroll
            for (int j = 0; j < 4; j++) s4[i][j] = 0.f;
#pragma unroll 4
        for (int d = 0; d < DH; d++) {
            float a[4], bb[4];
            *(float4*)a  = *(const float4*)&Qst[d * 64 + ty * 4];
            *(float4*)bb = *(const float4*)&Kst[d * 64 + tx * 4];
#pragma unroll
            for (int i = 0; i < 4; i++)
#pragma unroll
                for (int j = 0; j < 4; j++)
                    s4[i][j] = fmaf(a[i], bb[j], s4[i][j]);
        }

        // ---- online softmax ----
        const bool diag = (kb == qb);
#pragma unroll
        for (int i = 0; i < 4; i++) {
            int qg = qb * BQ + ty * 4 + i;
            float rm = -INFINITY;
#pragma unroll
            for (int j = 0; j < 4; j++) {
                float v = s4[i][j] * scale;
                if (diag) {
                    int kg = kb * BKV + tx * 4 + j;
                    if (kg > qg) v = -INFINITY;
                }
                s4[i][j] = v;
                rm = fmaxf(rm, v);
            }
#pragma unroll
            for (int off = 1; off < 16; off <<= 1)
                rm = fmaxf(rm, __shfl_xor_sync(0xffffffffu, rm, off));
            float mnew = fmaxf(m[i], rm);
            float alpha = __expf(m[i] - mnew);
            float rs = 0.f;
#pragma unroll
            for (int j = 0; j < 4; j++) {
                float p = __expf(s4[i][j] - mnew);
                s4[i][j] = p;
                rs += p;
            }
#pragma unroll
            for (int off = 1; off < 16; off <<= 1)
                rs += __shfl_xor_sync(0xffffffffu, rs, off);
            l[i] = l[i] * alpha + rs;
            m[i] = mnew;
#pragma unroll
            for (int j = 0; j < 8; j++) ctx[i][j] *= alpha;
#pragma unroll
            for (int j = 0; j < 4; j++)
                Pt[(tx * 4 + j) * 65 + ty * 4 + i] = s4[i][j];
        }
        __syncthreads();

        // ---- ctx += P @ V ----
#pragma unroll 2
        for (int k = 0; k < BKV; k++) {
            float a[4];
#pragma unroll
            for (int i = 0; i < 4; i++) a[i] = Pt[k * 65 + ty * 4 + i];
            float b0[4], b1[4];
            *(float4*)b0 = *(const float4*)&Vs[k * 128 + tx * 4];
            *(float4*)b1 = *(const float4*)&Vs[k * 128 + 64 + tx * 4];
#pragma unroll
            for (int i = 0; i < 4; i++) {
#pragma unroll
                for (int j = 0; j < 4; j++) {
                    ctx[i][j]     = fmaf(a[i], b0[j], ctx[i][j]);
                    ctx[i][4 + j] = fmaf(a[i], b1[j], ctx[i][4 + j]);
                }
            }
        }
    }

    // ---- epilogue: normalize and write [B*S, D] ----
#pragma unroll
    for (int i = 0; i < 4; i++) {
        float inv = 1.f / l[i];
        int qg = qb * BQ + ty * 4 + i;
        float* dst = ctxout + (size_t)(b * SS + qg) * DD + h * DH;
        float4 o0, o1;
        o0.x = ctx[i][0] * inv; o0.y = ctx[i][1] * inv;
        o0.z = ctx[i][2] * inv; o0.w = ctx[i][3] * inv;
        o1.x = ctx[i][4] * inv; o1.y = ctx[i][5] * inv;
        o1.z = ctx[i][6] * inv; o1.w = ctx[i][7] * inv;
        *(float4*)(dst + tx * 4)      = o0;
        *(float4*)(dst + 64 + tx * 4) = o1;
    }
}

// ---------------------------------------------------------------------------
// Residual add + LayerNorm: y = attn_out + x; ln = gamma*(y-mu)*rsqrt(var+eps)+beta
// One CTA (256 threads) per row of D=2048.
// ---------------------------------------------------------------------------
__global__ __launch_bounds__(256)
void mhsa_add_ln_kernel(const float* __restrict__ x, const float* __restrict__ ao,
                        const float* __restrict__ gamma, const float* __restrict__ beta,
                        float* __restrict__ ln)
{
    const int row = blockIdx.x;
    const int tid = threadIdx.x;
    const float4* xr = (const float4*)(x + (size_t)row * DD);
    const float4* ar = (const float4*)(ao + (size_t)row * DD);

    float4 y0, y1;
    {
        float4 xv = xr[tid], av = ar[tid];
        y0 = make_float4(xv.x + av.x, xv.y + av.y, xv.z + av.z, xv.w + av.w);
        xv = xr[tid + 256]; av = ar[tid + 256];
        y1 = make_float4(xv.x + av.x, xv.y + av.y, xv.z + av.z, xv.w + av.w);
    }
    float s  = y0.x + y0.y + y0.z + y0.w + y1.x + y1.y + y1.z + y1.w;
    float sq = y0.x*y0.x + y0.y*y0.y + y0.z*y0.z + y0.w*y0.w
             + y1.x*y1.x + y1.y*y1.y + y1.z*y1.z + y1.w*y1.w;

#pragma unroll
    for (int off = 16; off; off >>= 1) {
        s  += __shfl_xor_sync(0xffffffffu, s,  off);
        sq += __shfl_xor_sync(0xffffffffu, sq, off);
    }
    __shared__ float shs[8], shq[8];
    __shared__ float stats[2];
    int w = tid >> 5, lane = tid & 31;
    if (lane == 0) { shs[w] = s; shq[w] = sq; }
    __syncthreads();
    if (tid == 0) {
        float ts = 0.f, tq = 0.f;
#pragma unroll
        for (int i = 0; i < 8; i++) { ts += shs[i]; tq += shq[i]; }
        float mu = ts / (float)DD;
        float var = tq / (float)DD - mu * mu;
        stats[0] = mu;
        stats[1] = rsqrtf(var + 1e-5f);
    }
    __syncthreads();
    float mu = stats[0], rinv = stats[1];

    const float4* g4 = (const float4*)gamma;
    const float4* b4 = (const float4*)beta;
    float4* lr = (float4*)(ln + (size_t)row * DD);
    {
        float4 gv = g4[tid], bv = b4[tid];
        float4 o = make_float4(gv.x * (y0.x - mu) * rinv + bv.x,
                               gv.y * (y0.y - mu) * rinv + bv.y,
                               gv.z * (y0.z - mu) * rinv + bv.z,
                               gv.w * (y0.w - mu) * rinv + bv.w);
        lr[tid] = o;
        gv = g4[tid + 256]; bv = b4[tid + 256];
        o = make_float4(gv.x * (y1.x - mu) * rinv + bv.x,
                        gv.y * (y1.y - mu) * rinv + bv.y,
                        gv.z * (y1.z - mu) * rinv + bv.z,
                        gv.w * (y1.w - mu) * rinv + bv.w);
        lr[tid + 256] = o;
    }
}

// ---------------------------------------------------------------------------
// Launch: inputs (metadata order): x, Wq, bq, Wk, bk, Wv, bv, Wo, bo, gamma,
// beta, num_heads. Output tuple (ln, attn_out, k, v) flattened into d_out.
// ---------------------------------------------------------------------------
extern "C" void kernel_launch(void* const* d_in, const int* in_sizes, int n_in,
                              void* d_out, int out_size)
{
    const float* x     = (const float*)d_in[0];
    const float* Wq    = (const float*)d_in[1];
    const float* bq    = (const float*)d_in[2];
    const float* Wk    = (const float*)d_in[3];
    const float* bk    = (const float*)d_in[4];
    const float* Wv    = (const float*)d_in[5];
    const float* bv    = (const float*)d_in[6];
    const float* Wo    = (const float*)d_in[7];
    const float* bo    = (const float*)d_in[8];
    const float* gamma = (const float*)d_in[9];
    const float* beta  = (const float*)d_in[10];

    float* out      = (float*)d_out;
    const size_t SEC = (size_t)BB * SS * DD;   // 8388608
    float* out_ln   = out;
    float* out_ao   = out + SEC;
    float* out_k    = out + 2 * SEC;
    float* out_v    = out + 3 * SEC;

    float* qptr = nullptr;
    float* cptr = nullptr;
    cudaGetSymbolAddress((void**)&qptr, g_Q);
    cudaGetSymbolAddress((void**)&cptr, g_ctx);

    cudaFuncSetAttribute(mhsa_attn_kernel,
                         cudaFuncAttributeMaxDynamicSharedMemorySize,
                         ATT_SMEM_BYTES);

    dim3 ggrid(DD / GBN, MM / GBM);   // (16, 32)

    // Projections: Q -> scratch (row-major), K/V -> output slots ([B,H,S,Dh])
    mhsa_gemm_kernel<<<ggrid, 256>>>(x, Wq, bq, qptr, 0);
    mhsa_gemm_kernel<<<ggrid, 256>>>(x, Wk, bk, out_k, 1);
    mhsa_gemm_kernel<<<ggrid, 256>>>(x, Wv, bv, out_v, 1);

    // Flash attention (reads K/V from the output slots — they ARE the k,v outputs)
    dim3 agrid(SS / BQ, HH, BB);      // (32, 16, 2)
    mhsa_attn_kernel<<<agrid, 256, ATT_SMEM_BYTES>>>(qptr, out_k, out_v, cptr);

    // Output projection
    mhsa_gemm_kernel<<<ggrid, 256>>>(cptr, Wo, bo, out_ao, 0);

    // Residual + LayerNorm
    mhsa_add_ln_kernel<<<MM, 256>>>(x, out_ao, gamma, beta, out_ln);
}

// round 7
// speedup vs baseline: 2.0943x; 2.0943x over previous
#include <cuda_runtime.h>
#include <cuda_bf16.h>
#include <math.h>
#include <stdint.h>

// Problem constants: B=2, S=2048, D=2048, H=16, Dh=128
#define BB 2
#define SS 2048
#define DD 2048
#define HH 16
#define DH 128
#define MM (BB*SS)          // 4096 rows for the projection GEMMs

// ---------------------------------------------------------------------------
// Scratch (device globals — allocation-free per harness rules)
// ---------------------------------------------------------------------------
__device__ float g_Q[BB*SS*DD];    // Q projection, [B*S, D] row-major
__device__ float g_ctx[BB*SS*DD];  // attention context, [B*S, D] row-major

// ---------------------------------------------------------------------------
// PTX helpers (family-portable: mma.sync + cp.async only — NO tcgen05, the
// harness compiles via compute_103 base target which rejects "a" features)
// ---------------------------------------------------------------------------
__device__ __forceinline__ uint32_t smem_u32(const void* p) {
    uint32_t a;
    asm("{ .reg .u64 t; cvta.to.shared.u64 t, %1; cvt.u32.u64 %0, t; }" : "=r"(a) : "l"(p));
    return a;
}
__device__ __forceinline__ uint32_t f2tf32(float x) {
    uint32_t r;
    asm("cvt.rna.tf32.f32 %0, %1;" : "=r"(r) : "f"(x));
    return r;
}
__device__ __forceinline__ void mma_tf32(float d[4], const uint32_t a[4], const uint32_t b[2]) {
    asm volatile(
        "mma.sync.aligned.m16n8k8.row.col.f32.tf32.tf32.f32 "
        "{%0,%1,%2,%3}, {%4,%5,%6,%7}, {%8,%9}, {%0,%1,%2,%3};"
        : "+f"(d[0]), "+f"(d[1]), "+f"(d[2]), "+f"(d[3])
        : "r"(a[0]), "r"(a[1]), "r"(a[2]), "r"(a[3]), "r"(b[0]), "r"(b[1]));
}
#define CP_ASYNC16(saddr, gptr) \
    asm volatile("cp.async.cg.shared.global [%0], [%1], 16;" :: "r"(saddr), "l"(gptr) : "memory")
#define CP_COMMIT() asm volatile("cp.async.commit_group;" ::: "memory")
#define CP_WAIT1()  asm volatile("cp.async.wait_group 1;" ::: "memory")

// ---------------------------------------------------------------------------
// tf32 mma.sync GEMM: C[M,N] = A[M,K] @ W[K,N] + bias[N]
// M=4096, N=2048, K=2048. CTA 128x128, BK=32, 3-stage cp.async pipeline.
// 128 threads = 4 warps (2x2), warp tile 64x64 (m16n8k8 frags).
// Smem swizzle: A word (m,k) at m*32 + (k ^ ((m&7)*4))
//               B word (k,n) at k*128 + (n ^ ((k&3)*8))
// Both keep cp.async 16B contiguity and give conflict-free fragment LDS.
// mode 0: row-major store. mode 1: head-transposed store into [B,H,S,Dh].
// ---------------------------------------------------------------------------
#define TBM 128
#define TBN 128
#define TBK 32
#define TST 3
#define TNIT (DD / TBK)                   // 64
#define TSTAGE_F 8192                     // A 128*32 + B 32*128 floats
#define TSMEM_BYTES (TST * TSTAGE_F * 4)  // 98304

__device__ __forceinline__ void gemm_load_stage(
    float* sm, int s, int it, int tid,
    const float* __restrict__ Ab, const float* __restrict__ W, int bn)
{
    float* As = sm + s * TSTAGE_F;
    float* Bs = As + 4096;
    const int k0 = it * TBK;
    // A: 128 rows x 32 k-floats (8 float4 per thread)
#pragma unroll
    for (int j = 0; j < 8; j++) {
        int idx = j * 128 + tid;
        int row = idx >> 3;
        int c4  = (idx & 7) * 4;
        uint32_t dst = smem_u32(As + row * 32 + (c4 ^ ((row & 7) * 4)));
        CP_ASYNC16(dst, Ab + (size_t)row * DD + k0 + c4);
    }
    // B: 32 k-rows x 128 n-floats (8 float4 per thread)
#pragma unroll
    for (int j = 0; j < 8; j++) {
        int idx = j * 128 + tid;
        int krow = idx >> 5;
        int n4   = (idx & 31) * 4;
        uint32_t dst = smem_u32(Bs + krow * 128 + (n4 ^ ((krow & 3) * 8)));
        CP_ASYNC16(dst, W + (size_t)(k0 + krow) * DD + bn + n4);
    }
}

__global__ __launch_bounds__(128, 2)
void gemm_tf32(const float* __restrict__ A, const float* __restrict__ W,
               const float* __restrict__ bias, float* __restrict__ C, int mode)
{
    extern __shared__ float sm[];
    const int tid  = threadIdx.x;
    const int wid  = tid >> 5;
    const int lane = tid & 31;
    const int gid  = lane >> 2;   // 0..7
    const int tig  = lane & 3;    // 0..3
    const int wm   = wid >> 1;    // 0..1
    const int wn   = wid & 1;     // 0..1
    const int bm = blockIdx.y * TBM;
    const int bn = blockIdx.x * TBN;

    float acc[4][8][4];
#pragma unroll
    for (int i = 0; i < 4; i++)
#pragma unroll
        for (int j = 0; j < 8; j++)
#pragma unroll
            for (int c = 0; c < 4; c++) acc[i][j][c] = 0.f;

    const float* Ab = A + (size_t)bm * DD;

    // Prologue: stages 0,1
    gemm_load_stage(sm, 0, 0, tid, Ab, W, bn); CP_COMMIT();
    gemm_load_stage(sm, 1, 1, tid, Ab, W, bn); CP_COMMIT();

    for (int it = 0; it < TNIT; it++) {
        CP_WAIT1();
        __syncthreads();
        if (it + TST - 1 < TNIT)
            gemm_load_stage(sm, (it + TST - 1) % TST, it + TST - 1, tid, Ab, W, bn);
        CP_COMMIT();

        const float* As = sm + (it % TST) * TSTAGE_F;
        const float* Bs = As + 4096;
        const int abase = (wm * 64 + gid) * 32;
        const int axor  = gid * 4;

#pragma unroll
        for (int ks = 0; ks < 4; ks++) {
            const int kk  = ks * 8 + tig;
            const int kx0 = kk ^ axor;
            const int kx4 = (kk + 4) ^ axor;

            uint32_t af[4][4];
#pragma unroll
            for (int mf = 0; mf < 4; mf++) {
                const int r0 = abase + mf * 16 * 32;
                af[mf][0] = f2tf32(As[r0 + kx0]);
                af[mf][1] = f2tf32(As[r0 + 8 * 32 + kx0]);
                af[mf][2] = f2tf32(As[r0 + kx4]);
                af[mf][3] = f2tf32(As[r0 + 8 * 32 + kx4]);
            }
            uint32_t bf[8][2];
            const int brow0 = kk * 128;
            const int brow1 = (kk + 4) * 128;
            const int nxor  = tig * 8;
#pragma unroll
            for (int nf = 0; nf < 8; nf++) {
                const int nc = wn * 64 + ((nf * 8 + gid) ^ nxor);
                bf[nf][0] = f2tf32(Bs[brow0 + nc]);
                bf[nf][1] = f2tf32(Bs[brow1 + nc]);
            }
#pragma unroll
            for (int mf = 0; mf < 4; mf++)
#pragma unroll
                for (int nf = 0; nf < 8; nf++)
                    mma_tf32(acc[mf][nf], af[mf], bf[nf]);
        }
        __syncthreads();
    }

    // Epilogue: bias add + store
#pragma unroll
    for (int mf = 0; mf < 4; mf++) {
#pragma unroll
        for (int half = 0; half < 2; half++) {
            const int row = bm + wm * 64 + mf * 16 + gid + half * 8;
            float* dst;
            if (mode == 0) {
                dst = C + (size_t)row * DD + bn;
            } else {
                int b_ = row >> 11;
                int s_ = row & (SS - 1);
                int h_ = bn >> 7;
                dst = C + ((size_t)((b_ * HH + h_) * SS) + s_) * DH;  // d = col&127
            }
#pragma unroll
            for (int nf = 0; nf < 8; nf++) {
                const int cl = wn * 64 + nf * 8 + tig * 2;   // col - bn (= d for mode 1)
                float2 bv = *(const float2*)(bias + bn + cl);
                float2 v;
                v.x = acc[mf][nf][half * 2 + 0] + bv.x;
                v.y = acc[mf][nf][half * 2 + 1] + bv.y;
                *(float2*)(dst + cl) = v;
            }
        }
    }
}

// ---------------------------------------------------------------------------
// Causal flash attention (R4 kernel; launch_bounds(256,2) for occupancy 2).
// ---------------------------------------------------------------------------
#define BQ 64
#define BKV 64
#define ATT_SMEM_FLOATS (8192 + 8192 + 8192 + 64*65)
#define ATT_SMEM_BYTES  (ATT_SMEM_FLOATS * 4)

__global__ __launch_bounds__(256, 2)
void mhsa_attn_kernel(const float* __restrict__ Q, const float* __restrict__ K,
                      const float* __restrict__ V, float* __restrict__ ctxout)
{
    extern __shared__ float sm[];
    float* Qst = sm;              // [128][64]  Qst[d*64 + q]
    float* Kst = sm + 8192;       // [128][64]
    float* Vs  = sm + 16384;      // [64][128]
    float* Pt  = sm + 24576;      // [64][65]   Pt[k*65 + q]

    const int qb = blockIdx.x;
    const int h  = blockIdx.y;
    const int b  = blockIdx.z;
    const int tid = threadIdx.x;
    const int tx = tid & 15;
    const int ty = tid >> 4;
    const int lq  = tid & 31;
    const int ld4 = (tid >> 5) * 4;

    const float* Qbase = Q + (size_t)(b * SS + qb * BQ) * DD + h * DH;
#pragma unroll
    for (int qh = 0; qh < 2; qh++)
#pragma unroll
        for (int dh = 0; dh < 4; dh++) {
            int q = qh * 32 + lq;
            int d = dh * 32 + ld4;
            float4 v = *(const float4*)(Qbase + (size_t)q * DD + d);
            Qst[(d + 0) * 64 + q] = v.x;
            Qst[(d + 1) * 64 + q] = v.y;
            Qst[(d + 2) * 64 + q] = v.z;
            Qst[(d + 3) * 64 + q] = v.w;
        }

    float ctx[4][8];
    float m[4], l[4];
#pragma unroll
    for (int i = 0; i < 4; i++) {
        m[i] = -INFINITY; l[i] = 0.f;
#pragma unroll
        for (int j = 0; j < 8; j++) ctx[i][j] = 0.f;
    }

    const float scale = 0.08838834764831845f;  // 1/sqrt(128)
    const float* Kbh = K + (size_t)((b * HH + h) * SS) * DH;
    const float* Vbh = V + (size_t)((b * HH + h) * SS) * DH;

    for (int kb = 0; kb <= qb; kb++) {
        __syncthreads();
        const float* Kb = Kbh + (size_t)kb * BKV * DH;
        const float* Vb = Vbh + (size_t)kb * BKV * DH;
#pragma unroll
        for (int qh = 0; qh < 2; qh++)
#pragma unroll
            for (int dh = 0; dh < 4; dh++) {
                int k = qh * 32 + lq;
                int d = dh * 32 + ld4;
                float4 v = *(const float4*)(Kb + (size_t)k * DH + d);
                Kst[(d + 0) * 64 + k] = v.x;
                Kst[(d + 1) * 64 + k] = v.y;
                Kst[(d + 2) * 64 + k] = v.z;
                Kst[(d + 3) * 64 + k] = v.w;
            }
#pragma unroll
        for (int it = 0; it < 8; it++) {
            int idx = it * 256 + tid;
            ((float4*)Vs)[idx] = ((const float4*)Vb)[idx];
        }
        __syncthreads();

        float s4[4][4];
#pragma unroll
        for (int i = 0; i < 4; i++)
#pragma unroll
            for (int j = 0; j < 4; j++) s4[i][j] = 0.f;
#pragma unroll 4
        for (int d = 0; d < DH; d++) {
            float a[4], bb[4];
            *(float4*)a  = *(const float4*)&Qst[d * 64 + ty * 4];
            *(float4*)bb = *(const float4*)&Kst[d * 64 + tx * 4];
#pragma unroll
            for (int i = 0; i < 4; i++)
#pragma unroll
                for (int j = 0; j < 4; j++)
                    s4[i][j] = fmaf(a[i], bb[j], s4[i][j]);
        }

        const bool diag = (kb == qb);
#pragma unroll
        for (int i = 0; i < 4; i++) {
            int qg = qb * BQ + ty * 4 + i;
            float rm = -INFINITY;
#pragma unroll
            for (int j = 0; j < 4; j++) {
                float v = s4[i][j] * scale;
                if (diag) {
                    int kg = kb * BKV + tx * 4 + j;
                    if (kg > qg) v = -INFINITY;
                }
                s4[i][j] = v;
                rm = fmaxf(rm, v);
            }
#pragma unroll
            for (int off = 1; off < 16; off <<= 1)
                rm = fmaxf(rm, __shfl_xor_sync(0xffffffffu, rm, off));
            float mnew = fmaxf(m[i], rm);
            float alpha = __expf(m[i] - mnew);
            float rs = 0.f;
#pragma unroll
            for (int j = 0; j < 4; j++) {
                float p = __expf(s4[i][j] - mnew);
                s4[i][j] = p;
                rs += p;
            }
#pragma unroll
            for (int off = 1; off < 16; off <<= 1)
                rs += __shfl_xor_sync(0xffffffffu, rs, off);
            l[i] = l[i] * alpha + rs;
            m[i] = mnew;
#pragma unroll
            for (int j = 0; j < 8; j++) ctx[i][j] *= alpha;
#pragma unroll
            for (int j = 0; j < 4; j++)
                Pt[(tx * 4 + j) * 65 + ty * 4 + i] = s4[i][j];
        }
        __syncthreads();

#pragma unroll 2
        for (int k = 0; k < BKV; k++) {
            float a[4];
#pragma unroll
            for (int i = 0; i < 4; i++) a[i] = Pt[k * 65 + ty * 4 + i];
            float b0[4], b1[4];
            *(float4*)b0 = *(const float4*)&Vs[k * 128 + tx * 4];
            *(float4*)b1 = *(const float4*)&Vs[k * 128 + 64 + tx * 4];
#pragma unroll
            for (int i = 0; i < 4; i++) {
#pragma unroll
                for (int j = 0; j < 4; j++) {
                    ctx[i][j]     = fmaf(a[i], b0[j], ctx[i][j]);
                    ctx[i][4 + j] = fmaf(a[i], b1[j], ctx[i][4 + j]);
                }
            }
        }
    }

#pragma unroll
    for (int i = 0; i < 4; i++) {
        float inv = 1.f / l[i];
        int qg = qb * BQ + ty * 4 + i;
        float* dst = ctxout + (size_t)(b * SS + qg) * DD + h * DH;
        float4 o0, o1;
        o0.x = ctx[i][0] * inv; o0.y = ctx[i][1] * inv;
        o0.z = ctx[i][2] * inv; o0.w = ctx[i][3] * inv;
        o1.x = ctx[i][4] * inv; o1.y = ctx[i][5] * inv;
        o1.z = ctx[i][6] * inv; o1.w = ctx[i][7] * inv;
        *(float4*)(dst + tx * 4)      = o0;
        *(float4*)(dst + 64 + tx * 4) = o1;
    }
}

// ---------------------------------------------------------------------------
// Residual add + LayerNorm
// ---------------------------------------------------------------------------
__global__ __launch_bounds__(256)
void mhsa_add_ln_kernel(const float* __restrict__ x, const float* __restrict__ ao,
                        const float* __restrict__ gamma, const float* __restrict__ beta,
                        float* __restrict__ ln)
{
    const int row = blockIdx.x;
    const int tid = threadIdx.x;
    const float4* xr = (const float4*)(x + (size_t)row * DD);
    const float4* ar = (const float4*)(ao + (size_t)row * DD);

    float4 y0, y1;
    {
        float4 xv = xr[tid], av = ar[tid];
        y0 = make_float4(xv.x + av.x, xv.y + av.y, xv.z + av.z, xv.w + av.w);
        xv = xr[tid + 256]; av = ar[tid + 256];
        y1 = make_float4(xv.x + av.x, xv.y + av.y, xv.z + av.z, xv.w + av.w);
    }
    float s  = y0.x + y0.y + y0.z + y0.w + y1.x + y1.y + y1.z + y1.w;
    float sq = y0.x*y0.x + y0.y*y0.y + y0.z*y0.z + y0.w*y0.w
             + y1.x*y1.x + y1.y*y1.y + y1.z*y1.z + y1.w*y1.w;

#pragma unroll
    for (int off = 16; off; off >>= 1) {
        s  += __shfl_xor_sync(0xffffffffu, s,  off);
        sq += __shfl_xor_sync(0xffffffffu, sq, off);
    }
    __shared__ float shs[8], shq[8];
    __shared__ float stats[2];
    int w = tid >> 5, lane = tid & 31;
    if (lane == 0) { shs[w] = s; shq[w] = sq; }
    __syncthreads();
    if (tid == 0) {
        float ts = 0.f, tq = 0.f;
#pragma unroll
        for (int i = 0; i < 8; i++) { ts += shs[i]; tq += shq[i]; }
        float mu = ts / (float)DD;
        float var = tq / (float)DD - mu * mu;
        stats[0] = mu;
        stats[1] = rsqrtf(var + 1e-5f);
    }
    __syncthreads();
    float mu = stats[0], rinv = stats[1];

    const float4* g4 = (const float4*)gamma;
    const float4* b4 = (const float4*)beta;
    float4* lr = (float4*)(ln + (size_t)row * DD);
    {
        float4 gv = g4[tid], bv = b4[tid];
        float4 o = make_float4(gv.x * (y0.x - mu) * rinv + bv.x,
                               gv.y * (y0.y - mu) * rinv + bv.y,
                               gv.z * (y0.z - mu) * rinv + bv.z,
                               gv.w * (y0.w - mu) * rinv + bv.w);
        lr[tid] = o;
        gv = g4[tid + 256]; bv = b4[tid + 256];
        o = make_float4(gv.x * (y1.x - mu) * rinv + bv.x,
                        gv.y * (y1.y - mu) * rinv + bv.y,
                        gv.z * (y1.z - mu) * rinv + bv.z,
                        gv.w * (y1.w - mu) * rinv + bv.w);
        lr[tid + 256] = o;
    }
}

// ---------------------------------------------------------------------------
// Launch. Inputs: x, Wq, bq, Wk, bk, Wv, bv, Wo, bo, gamma, beta, num_heads.
// Output tuple (ln, attn_out, k, v) flattened into d_out.
// ---------------------------------------------------------------------------
extern "C" void kernel_launch(void* const* d_in, const int* in_sizes, int n_in,
                              void* d_out, int out_size)
{
    const float* x     = (const float*)d_in[0];
    const float* Wq    = (const float*)d_in[1];
    const float* bq    = (const float*)d_in[2];
    const float* Wk    = (const float*)d_in[3];
    const float* bk    = (const float*)d_in[4];
    const float* Wv    = (const float*)d_in[5];
    const float* bv    = (const float*)d_in[6];
    const float* Wo    = (const float*)d_in[7];
    const float* bo    = (const float*)d_in[8];
    const float* gamma = (const float*)d_in[9];
    const float* beta  = (const float*)d_in[10];

    float* out      = (float*)d_out;
    const size_t SEC = (size_t)BB * SS * DD;   // 8388608
    float* out_ln   = out;
    float* out_ao   = out + SEC;
    float* out_k    = out + 2 * SEC;
    float* out_v    = out + 3 * SEC;

    float* qptr = nullptr;
    float* cptr = nullptr;
    cudaGetSymbolAddress((void**)&qptr, g_Q);
    cudaGetSymbolAddress((void**)&cptr, g_ctx);

    cudaFuncSetAttribute(mhsa_attn_kernel,
                         cudaFuncAttributeMaxDynamicSharedMemorySize, ATT_SMEM_BYTES);
    cudaFuncSetAttribute(gemm_tf32,
                         cudaFuncAttributeMaxDynamicSharedMemorySize, TSMEM_BYTES);

    dim3 ggrid(DD / TBN, MM / TBM);   // (16, 32)

    // Projections: Q -> scratch (row-major), K/V -> output slots ([B,H,S,Dh])
    gemm_tf32<<<ggrid, 128, TSMEM_BYTES>>>(x, Wq, bq, qptr, 0);
    gemm_tf32<<<ggrid, 128, TSMEM_BYTES>>>(x, Wk, bk, out_k, 1);
    gemm_tf32<<<ggrid, 128, TSMEM_BYTES>>>(x, Wv, bv, out_v, 1);

    // Flash attention (reads K/V from the output slots — they ARE the k,v outputs)
    dim3 agrid(SS / BQ, HH, BB);      // (32, 16, 2)
    mhsa_attn_kernel<<<agrid, 256, ATT_SMEM_BYTES>>>(qptr, out_k, out_v, cptr);

    // Output projection
    gemm_tf32<<<ggrid, 128, TSMEM_BYTES>>>(cptr, Wo, bo, out_ao, 0);

    // Residual + LayerNorm
    mhsa_add_ln_kernel<<<MM, 256>>>(x, out_ao, gamma, beta, out_ln);
}

// round 8
// speedup vs baseline: 3.5757x; 1.7074x over previous
#include <cuda_runtime.h>
#include <cuda_bf16.h>
#include <math.h>
#include <stdint.h>

// Problem constants: B=2, S=2048, D=2048, H=16, Dh=128
#define BB 2
#define SS 2048
#define DD 2048
#define HH 16
#define DH 128
#define MM (BB*SS)          // 4096 rows for the projection GEMMs

// ---------------------------------------------------------------------------
// Scratch (device globals — allocation-free per harness rules)
// ---------------------------------------------------------------------------
__device__ float g_Q[BB*SS*DD];    // Q projection, [B*S, D] row-major
__device__ float g_ctx[BB*SS*DD];  // attention context, [B*S, D] row-major

// ---------------------------------------------------------------------------
// PTX helpers (family-portable: mma.sync + cp.async only — NO tcgen05, the
// harness compiles via compute_103 base target which rejects "a" features)
// ---------------------------------------------------------------------------
__device__ __forceinline__ uint32_t smem_u32(const void* p) {
    uint32_t a;
    asm("{ .reg .u64 t; cvta.to.shared.u64 t, %1; cvt.u32.u64 %0, t; }" : "=r"(a) : "l"(p));
    return a;
}
__device__ __forceinline__ uint32_t f2tf32(float x) {
    uint32_t r;
    asm("cvt.rna.tf32.f32 %0, %1;" : "=r"(r) : "f"(x));
    return r;
}
__device__ __forceinline__ void mma_tf32(float d[4], const uint32_t a[4], const uint32_t b[2]) {
    asm volatile(
        "mma.sync.aligned.m16n8k8.row.col.f32.tf32.tf32.f32 "
        "{%0,%1,%2,%3}, {%4,%5,%6,%7}, {%8,%9}, {%0,%1,%2,%3};"
        : "+f"(d[0]), "+f"(d[1]), "+f"(d[2]), "+f"(d[3])
        : "r"(a[0]), "r"(a[1]), "r"(a[2]), "r"(a[3]), "r"(b[0]), "r"(b[1]));
}
#define CP_ASYNC16(saddr, gptr) \
    asm volatile("cp.async.cg.shared.global [%0], [%1], 16;" :: "r"(saddr), "l"(gptr) : "memory")
#define CP_COMMIT() asm volatile("cp.async.commit_group;" ::: "memory")
#define CP_WAIT0()  asm volatile("cp.async.wait_group 0;" ::: "memory")
#define CP_WAIT1()  asm volatile("cp.async.wait_group 1;" ::: "memory")

// ---------------------------------------------------------------------------
// tf32 mma.sync GEMM (unchanged from R6 — passing): C = A @ W + bias
// ---------------------------------------------------------------------------
#define TBM 128
#define TBN 128
#define TBK 32
#define TST 3
#define TNIT (DD / TBK)                   // 64
#define TSTAGE_F 8192                     // A 128*32 + B 32*128 floats
#define TSMEM_BYTES (TST * TSTAGE_F * 4)  // 98304

__device__ __forceinline__ void gemm_load_stage(
    float* sm, int s, int it, int tid,
    const float* __restrict__ Ab, const float* __restrict__ W, int bn)
{
    float* As = sm + s * TSTAGE_F;
    float* Bs = As + 4096;
    const int k0 = it * TBK;
#pragma unroll
    for (int j = 0; j < 8; j++) {
        int idx = j * 128 + tid;
        int row = idx >> 3;
        int c4  = (idx & 7) * 4;
        uint32_t dst = smem_u32(As + row * 32 + (c4 ^ ((row & 7) * 4)));
        CP_ASYNC16(dst, Ab + (size_t)row * DD + k0 + c4);
    }
#pragma unroll
    for (int j = 0; j < 8; j++) {
        int idx = j * 128 + tid;
        int krow = idx >> 5;
        int n4   = (idx & 31) * 4;
        uint32_t dst = smem_u32(Bs + krow * 128 + (n4 ^ ((krow & 3) * 8)));
        CP_ASYNC16(dst, W + (size_t)(k0 + krow) * DD + bn + n4);
    }
}

__global__ __launch_bounds__(128, 2)
void gemm_tf32(const float* __restrict__ A, const float* __restrict__ W,
               const float* __restrict__ bias, float* __restrict__ C, int mode)
{
    extern __shared__ float sm[];
    const int tid  = threadIdx.x;
    const int wid  = tid >> 5;
    const int lane = tid & 31;
    const int gid  = lane >> 2;
    const int tig  = lane & 3;
    const int wm   = wid >> 1;
    const int wn   = wid & 1;
    const int bm = blockIdx.y * TBM;
    const int bn = blockIdx.x * TBN;

    float acc[4][8][4];
#pragma unroll
    for (int i = 0; i < 4; i++)
#pragma unroll
        for (int j = 0; j < 8; j++)
#pragma unroll
            for (int c = 0; c < 4; c++) acc[i][j][c] = 0.f;

    const float* Ab = A + (size_t)bm * DD;

    gemm_load_stage(sm, 0, 0, tid, Ab, W, bn); CP_COMMIT();
    gemm_load_stage(sm, 1, 1, tid, Ab, W, bn); CP_COMMIT();

    for (int it = 0; it < TNIT; it++) {
        CP_WAIT1();
        __syncthreads();
        if (it + TST - 1 < TNIT)
            gemm_load_stage(sm, (it + TST - 1) % TST, it + TST - 1, tid, Ab, W, bn);
        CP_COMMIT();

        const float* As = sm + (it % TST) * TSTAGE_F;
        const float* Bs = As + 4096;
        const int abase = (wm * 64 + gid) * 32;
        const int axor  = gid * 4;

#pragma unroll
        for (int ks = 0; ks < 4; ks++) {
            const int kk  = ks * 8 + tig;
            const int kx0 = kk ^ axor;
            const int kx4 = (kk + 4) ^ axor;

            uint32_t af[4][4];
#pragma unroll
            for (int mf = 0; mf < 4; mf++) {
                const int r0 = abase + mf * 16 * 32;
                af[mf][0] = f2tf32(As[r0 + kx0]);
                af[mf][1] = f2tf32(As[r0 + 8 * 32 + kx0]);
                af[mf][2] = f2tf32(As[r0 + kx4]);
                af[mf][3] = f2tf32(As[r0 + 8 * 32 + kx4]);
            }
            uint32_t bf[8][2];
            const int brow0 = kk * 128;
            const int brow1 = (kk + 4) * 128;
            const int nxor  = tig * 8;
#pragma unroll
            for (int nf = 0; nf < 8; nf++) {
                const int nc = wn * 64 + ((nf * 8 + gid) ^ nxor);
                bf[nf][0] = f2tf32(Bs[brow0 + nc]);
                bf[nf][1] = f2tf32(Bs[brow1 + nc]);
            }
#pragma unroll
            for (int mf = 0; mf < 4; mf++)
#pragma unroll
                for (int nf = 0; nf < 8; nf++)
                    mma_tf32(acc[mf][nf], af[mf], bf[nf]);
        }
        __syncthreads();
    }

#pragma unroll
    for (int mf = 0; mf < 4; mf++) {
#pragma unroll
        for (int half = 0; half < 2; half++) {
            const int row = bm + wm * 64 + mf * 16 + gid + half * 8;
            float* dst;
            if (mode == 0) {
                dst = C + (size_t)row * DD + bn;
            } else {
                int b_ = row >> 11;
                int s_ = row & (SS - 1);
                int h_ = bn >> 7;
                dst = C + ((size_t)((b_ * HH + h_) * SS) + s_) * DH;
            }
#pragma unroll
            for (int nf = 0; nf < 8; nf++) {
                const int cl = wn * 64 + nf * 8 + tig * 2;
                float2 bv = *(const float2*)(bias + bn + cl);
                float2 v;
                v.x = acc[mf][nf][half * 2 + 0] + bv.x;
                v.y = acc[mf][nf][half * 2 + 1] + bv.y;
                *(float2*)(dst + cl) = v;
            }
        }
    }
}

// ---------------------------------------------------------------------------
// Tensor-core causal flash attention.
// CTA: 128 q-rows x full head. 8 warps, each warp owns 16 q-rows.
// KV tiles of 64, double-buffered cp.async, row-major with padded strides:
//   Ks stride 132 (QK B-frag banks (4g+t): conflict-free)
//   Vs stride 136 (PV B-frag banks (8t+g): conflict-free)
// P round-trips via warp-private smem (stride 68, tf32-prequantized).
// ---------------------------------------------------------------------------
#define AQ 128
#define AKV 64
#define KS_STR 132
#define VS_STR 136
#define PS_STR 68
#define A2_KS_F (2 * AKV * KS_STR)      // 16896 floats
#define A2_VS_F (2 * AKV * VS_STR)      // 17408
#define A2_PS_F (AQ * PS_STR)           // 8704
#define A2_SMEM_BYTES ((A2_KS_F + A2_VS_F + A2_PS_F) * 4)   // 172032

__device__ __forceinline__ void attn_load_kv(
    float* Ks, float* Vs, int stage, int kb, int tid,
    const float* __restrict__ Kbh, const float* __restrict__ Vbh)
{
    const float* Kb = Kbh + (size_t)kb * AKV * DH;
    const float* Vb = Vbh + (size_t)kb * AKV * DH;
    float* Kd = Ks + stage * AKV * KS_STR;
    float* Vd = Vs + stage * AKV * VS_STR;
#pragma unroll
    for (int j = 0; j < 8; j++) {
        int idx = j * 256 + tid;        // 0..2047 (64 rows x 32 chunks)
        int row = idx >> 5;
        int c4  = (idx & 31) * 4;
        CP_ASYNC16(smem_u32(Kd + row * KS_STR + c4), Kb + (size_t)row * DH + c4);
    }
#pragma unroll
    for (int j = 0; j < 8; j++) {
        int idx = j * 256 + tid;
        int row = idx >> 5;
        int c4  = (idx & 31) * 4;
        CP_ASYNC16(smem_u32(Vd + row * VS_STR + c4), Vb + (size_t)row * DH + c4);
    }
}

__global__ __launch_bounds__(256, 1)
void attn_tc(const float* __restrict__ Q, const float* __restrict__ K,
             const float* __restrict__ V, float* __restrict__ ctxout)
{
    extern __shared__ float sm[];
    float* Ks = sm;
    float* Vs = sm + A2_KS_F;
    float* Ps = Vs + A2_VS_F;

    const int qb = blockIdx.x;          // 0..15
    const int h  = blockIdx.y;
    const int b  = blockIdx.z;
    const int tid = threadIdx.x;
    const int w   = tid >> 5;           // warp 0..7, owns q-rows 16w..16w+15
    const int lane = tid & 31;
    const int g = lane >> 2;            // 0..7
    const int t = lane & 3;             // 0..3

    const float* Qbase = Q + (size_t)(b * SS + qb * AQ) * DD + h * DH;
    const float* Kbh = K + (size_t)((b * HH + h) * SS) * DH;
    const float* Vbh = V + (size_t)((b * HH + h) * SS) * DH;

    // ---- stage Q tile into Ks area (128 rows x 128, stride 132), coalesced ----
#pragma unroll
    for (int j = 0; j < 16; j++) {
        int idx = j * 256 + tid;        // 0..4095 (128 rows x 32 chunks)
        int row = idx >> 5;
        int c4  = (idx & 31) * 4;
        CP_ASYNC16(smem_u32(Ks + row * KS_STR + c4), Qbase + (size_t)row * DD + c4);
    }
    CP_COMMIT();
    CP_WAIT0();
    __syncthreads();

    // ---- Q fragments (pre-scaled, tf32) held in registers for whole CTA ----
    uint32_t qf[16][4];
    {
        const float scale = 0.08838834764831845f;   // 1/sqrt(128)
        const float* qr0 = Ks + (w * 16 + g) * KS_STR;
        const float* qr1 = qr0 + 8 * KS_STR;
#pragma unroll
        for (int kk = 0; kk < 16; kk++) {
            qf[kk][0] = f2tf32(qr0[kk * 8 + t] * scale);
            qf[kk][1] = f2tf32(qr1[kk * 8 + t] * scale);
            qf[kk][2] = f2tf32(qr0[kk * 8 + t + 4] * scale);
            qf[kk][3] = f2tf32(qr1[kk * 8 + t + 4] * scale);
        }
    }
    __syncthreads();

    float ctx[16][4];
#pragma unroll
    for (int i = 0; i < 16; i++)
#pragma unroll
        for (int c = 0; c < 4; c++) ctx[i][c] = 0.f;
    float m0 = -INFINITY, m1 = -INFINITY, l0 = 0.f, l1 = 0.f;

    const int nkb = 2 * qb + 2;
    const int qrow0 = qb * AQ + w * 16 + g;      // global q row of c0,c1
    uint32_t* Pw = (uint32_t*)(Ps + (w * 16 + g) * PS_STR);  // this thread's row0
    const uint32_t* Pr0 = (const uint32_t*)Ps + (w * 16 + g) * PS_STR;
    const uint32_t* Pr1 = Pr0 + 8 * PS_STR;

    attn_load_kv(Ks, Vs, 0, 0, tid, Kbh, Vbh);
    CP_COMMIT();

    for (int kb = 0; kb < nkb; kb++) {
        if (kb + 1 < nkb) {
            attn_load_kv(Ks, Vs, (kb + 1) & 1, kb + 1, tid, Kbh, Vbh);
            CP_COMMIT();
            CP_WAIT1();
        } else {
            CP_WAIT0();
        }
        __syncthreads();

        // fully-masked warp on diagonal block: skip compute (no-op update)
        const bool skip = (kb * AKV > qb * AQ + w * 16 + 15);
        if (!skip) {
            const float* Kst = Ks + (kb & 1) * AKV * KS_STR;
            const float* Vst = Vs + (kb & 1) * AKV * VS_STR;

            // ---- S = Q K^T : 8 n-frags (kv) x 16 k-steps (d) ----
            float sf[8][4];
#pragma unroll
            for (int nf = 0; nf < 8; nf++)
#pragma unroll
                for (int c = 0; c < 4; c++) sf[nf][c] = 0.f;

#pragma unroll
            for (int kk = 0; kk < 16; kk++) {
#pragma unroll
                for (int nf = 0; nf < 8; nf++) {
                    uint32_t bf[2];
                    const float* kp = Kst + (nf * 8 + g) * KS_STR + kk * 8 + t;
                    bf[0] = f2tf32(kp[0]);
                    bf[1] = f2tf32(kp[4]);
                    mma_tf32(sf[nf], qf[kk], bf);
                }
            }

            // ---- causal mask (only near diagonal) ----
            if (kb * AKV + 63 > qb * AQ + w * 16) {
#pragma unroll
                for (int nf = 0; nf < 8; nf++) {
                    int kv = kb * AKV + nf * 8 + 2 * t;
                    if (kv     > qrow0)     sf[nf][0] = -1e30f;
                    if (kv + 1 > qrow0)     sf[nf][1] = -1e30f;
                    if (kv     > qrow0 + 8) sf[nf][2] = -1e30f;
                    if (kv + 1 > qrow0 + 8) sf[nf][3] = -1e30f;
                }
            }

            // ---- online softmax (rows qrow0, qrow0+8; state in 4-lane group) --
            float rm0 = -1e30f, rm1 = -1e30f;
#pragma unroll
            for (int nf = 0; nf < 8; nf++) {
                rm0 = fmaxf(rm0, fmaxf(sf[nf][0], sf[nf][1]));
                rm1 = fmaxf(rm1, fmaxf(sf[nf][2], sf[nf][3]));
            }
            rm0 = fmaxf(rm0, __shfl_xor_sync(0xffffffffu, rm0, 1));
            rm0 = fmaxf(rm0, __shfl_xor_sync(0xffffffffu, rm0, 2));
            rm1 = fmaxf(rm1, __shfl_xor_sync(0xffffffffu, rm1, 1));
            rm1 = fmaxf(rm1, __shfl_xor_sync(0xffffffffu, rm1, 2));

            float mn0 = fmaxf(m0, rm0), mn1 = fmaxf(m1, rm1);
            float al0 = __expf(m0 - mn0), al1 = __expf(m1 - mn1);
            float s0 = 0.f, s1 = 0.f;

#pragma unroll
            for (int nf = 0; nf < 8; nf++) {
                float p0 = __expf(sf[nf][0] - mn0);
                float p1 = __expf(sf[nf][1] - mn0);
                float p2 = __expf(sf[nf][2] - mn1);
                float p3 = __expf(sf[nf][3] - mn1);
                s0 += p0 + p1;
                s1 += p2 + p3;
                // store P pre-quantized to tf32 bits (A-frag loads skip cvt)
                uint2 v0 = make_uint2(f2tf32(p0), f2tf32(p1));
                uint2 v1 = make_uint2(f2tf32(p2), f2tf32(p3));
                *(uint2*)(Pw + nf * 8 + 2 * t)                = v0;
                *(uint2*)(Pw + 8 * PS_STR + nf * 8 + 2 * t)   = v1;
            }
            s0 += __shfl_xor_sync(0xffffffffu, s0, 1);
            s0 += __shfl_xor_sync(0xffffffffu, s0, 2);
            s1 += __shfl_xor_sync(0xffffffffu, s1, 1);
            s1 += __shfl_xor_sync(0xffffffffu, s1, 2);
            l0 = l0 * al0 + s0;
            l1 = l1 * al1 + s1;
            m0 = mn0; m1 = mn1;

#pragma unroll
            for (int nf = 0; nf < 16; nf++) {
                ctx[nf][0] *= al0; ctx[nf][1] *= al0;
                ctx[nf][2] *= al1; ctx[nf][3] *= al1;
            }
            __syncwarp();

            // ---- ctx += P @ V : 16 n-frags (d) x 8 k-steps (kv) ----
#pragma unroll
            for (int kk = 0; kk < 8; kk++) {
                uint32_t af[4];
                af[0] = Pr0[kk * 8 + t];
                af[1] = Pr1[kk * 8 + t];
                af[2] = Pr0[kk * 8 + t + 4];
                af[3] = Pr1[kk * 8 + t + 4];
#pragma unroll
                for (int nf = 0; nf < 16; nf++) {
                    uint32_t bf[2];
                    const float* vp = Vst + (kk * 8 + t) * VS_STR + nf * 8 + g;
                    bf[0] = f2tf32(vp[0]);
                    bf[1] = f2tf32(vp[4 * VS_STR]);
                    mma_tf32(ctx[nf], af, bf);
                }
            }
        }
        __syncthreads();
    }

    // ---- epilogue: normalize, write to [B*S, D] ----
    const float inv0 = 1.f / l0;
    const float inv1 = 1.f / l1;
    float* d0 = ctxout + (size_t)(b * SS + qrow0) * DD + h * DH;
    float* d1 = d0 + (size_t)8 * DD;
#pragma unroll
    for (int nf = 0; nf < 16; nf++) {
        float2 v0 = make_float2(ctx[nf][0] * inv0, ctx[nf][1] * inv0);
        float2 v1 = make_float2(ctx[nf][2] * inv1, ctx[nf][3] * inv1);
        *(float2*)(d0 + nf * 8 + 2 * t) = v0;
        *(float2*)(d1 + nf * 8 + 2 * t) = v1;
    }
}

// ---------------------------------------------------------------------------
// Residual add + LayerNorm (unchanged)
// ---------------------------------------------------------------------------
__global__ __launch_bounds__(256)
void mhsa_add_ln_kernel(const float* __restrict__ x, const float* __restrict__ ao,
                        const float* __restrict__ gamma, const float* __restrict__ beta,
                        float* __restrict__ ln)
{
    const int row = blockIdx.x;
    const int tid = threadIdx.x;
    const float4* xr = (const float4*)(x + (size_t)row * DD);
    const float4* ar = (const float4*)(ao + (size_t)row * DD);

    float4 y0, y1;
    {
        float4 xv = xr[tid], av = ar[tid];
        y0 = make_float4(xv.x + av.x, xv.y + av.y, xv.z + av.z, xv.w + av.w);
        xv = xr[tid + 256]; av = ar[tid + 256];
        y1 = make_float4(xv.x + av.x, xv.y + av.y, xv.z + av.z, xv.w + av.w);
    }
    float s  = y0.x + y0.y + y0.z + y0.w + y1.x + y1.y + y1.z + y1.w;
    float sq = y0.x*y0.x + y0.y*y0.y + y0.z*y0.z + y0.w*y0.w
             + y1.x*y1.x + y1.y*y1.y + y1.z*y1.z + y1.w*y1.w;

#pragma unroll
    for (int off = 16; off; off >>= 1) {
        s  += __shfl_xor_sync(0xffffffffu, s,  off);
        sq += __shfl_xor_sync(0xffffffffu, sq, off);
    }
    __shared__ float shs[8], shq[8];
    __shared__ float stats[2];
    int w = tid >> 5, lane = tid & 31;
    if (lane == 0) { shs[w] = s; shq[w] = sq; }
    __syncthreads();
    if (tid == 0) {
        float ts = 0.f, tq = 0.f;
#pragma unroll
        for (int i = 0; i < 8; i++) { ts += shs[i]; tq += shq[i]; }
        float mu = ts / (float)DD;
        float var = tq / (float)DD - mu * mu;
        stats[0] = mu;
        stats[1] = rsqrtf(var + 1e-5f);
    }
    __syncthreads();
    float mu = stats[0], rinv = stats[1];

    const float4* g4 = (const float4*)gamma;
    const float4* b4 = (const float4*)beta;
    float4* lr = (float4*)(ln + (size_t)row * DD);
    {
        float4 gv = g4[tid], bv = b4[tid];
        float4 o = make_float4(gv.x * (y0.x - mu) * rinv + bv.x,
                               gv.y * (y0.y - mu) * rinv + bv.y,
                               gv.z * (y0.z - mu) * rinv + bv.z,
                               gv.w * (y0.w - mu) * rinv + bv.w);
        lr[tid] = o;
        gv = g4[tid + 256]; bv = b4[tid + 256];
        o = make_float4(gv.x * (y1.x - mu) * rinv + bv.x,
                        gv.y * (y1.y - mu) * rinv + bv.y,
                        gv.z * (y1.z - mu) * rinv + bv.z,
                        gv.w * (y1.w - mu) * rinv + bv.w);
        lr[tid + 256] = o;
    }
}

// ---------------------------------------------------------------------------
// Launch. Inputs: x, Wq, bq, Wk, bk, Wv, bv, Wo, bo, gamma, beta, num_heads.
// Output tuple (ln, attn_out, k, v) flattened into d_out.
// ---------------------------------------------------------------------------
extern "C" void kernel_launch(void* const* d_in, const int* in_sizes, int n_in,
                              void* d_out, int out_size)
{
    const float* x     = (const float*)d_in[0];
    const float* Wq    = (const float*)d_in[1];
    const float* bq    = (const float*)d_in[2];
    const float* Wk    = (const float*)d_in[3];
    const float* bk    = (const float*)d_in[4];
    const float* Wv    = (const float*)d_in[5];
    const float* bv    = (const float*)d_in[6];
    const float* Wo    = (const float*)d_in[7];
    const float* bo    = (const float*)d_in[8];
    const float* gamma = (const float*)d_in[9];
    const float* beta  = (const float*)d_in[10];

    float* out      = (float*)d_out;
    const size_t SEC = (size_t)BB * SS * DD;   // 8388608
    float* out_ln   = out;
    float* out_ao   = out + SEC;
    float* out_k    = out + 2 * SEC;
    float* out_v    = out + 3 * SEC;

    float* qptr = nullptr;
    float* cptr = nullptr;
    cudaGetSymbolAddress((void**)&qptr, g_Q);
    cudaGetSymbolAddress((void**)&cptr, g_ctx);

    cudaFuncSetAttribute(attn_tc,
                         cudaFuncAttributeMaxDynamicSharedMemorySize, A2_SMEM_BYTES);
    cudaFuncSetAttribute(gemm_tf32,
                         cudaFuncAttributeMaxDynamicSharedMemorySize, TSMEM_BYTES);

    dim3 ggrid(DD / TBN, MM / TBM);   // (16, 32)

    // Projections: Q -> scratch (row-major), K/V -> output slots ([B,H,S,Dh])
    gemm_tf32<<<ggrid, 128, TSMEM_BYTES>>>(x, Wq, bq, qptr, 0);
    gemm_tf32<<<ggrid, 128, TSMEM_BYTES>>>(x, Wk, bk, out_k, 1);
    gemm_tf32<<<ggrid, 128, TSMEM_BYTES>>>(x, Wv, bv, out_v, 1);

    // Tensor-core flash attention (K/V read from output slots)
    dim3 agrid(SS / AQ, HH, BB);      // (16, 16, 2)
    attn_tc<<<agrid, 256, A2_SMEM_BYTES>>>(qptr, out_k, out_v, cptr);

    // Output projection
    gemm_tf32<<<ggrid, 128, TSMEM_BYTES>>>(cptr, Wo, bo, out_ao, 0);

    // Residual + LayerNorm
    mhsa_add_ln_kernel<<<MM, 256>>>(x, out_ao, gamma, beta, out_ln);
}

// round 9
// speedup vs baseline: 3.8134x; 1.0665x over previous
#include <cuda_runtime.h>
#include <cuda_bf16.h>
#include <math.h>
#include <stdint.h>

// Problem constants: B=2, S=2048, D=2048, H=16, Dh=128
#define BB 2
#define SS 2048
#define DD 2048
#define HH 16
#define DH 128
#define MM (BB*SS)          // 4096 rows for the projection GEMMs

// ---------------------------------------------------------------------------
// Scratch (device globals — allocation-free per harness rules)
// ---------------------------------------------------------------------------
__device__ float    g_Q[BB*SS*DD];      // Q projection (fp32)
__device__ float    g_ctx[BB*SS*DD];    // attention context (fp32)
__device__ uint32_t g_xq[MM*DD];        // x, tf32 bits
__device__ uint32_t g_wq[4ull*DD*DD];   // Wq,Wk,Wv,Wo, tf32 bits
__device__ uint32_t g_kq[BB*SS*DD];     // k output, tf32 bits ([B,H,S,Dh])
__device__ uint32_t g_vq[BB*SS*DD];     // v output, tf32 bits
__device__ uint32_t g_cq[BB*SS*DD];     // ctx, tf32 bits

// ---------------------------------------------------------------------------
// PTX helpers (family-portable: mma.sync + cp.async only — NO tcgen05, the
// harness compiles via compute_103 base target which rejects "a" features)
// ---------------------------------------------------------------------------
__device__ __forceinline__ uint32_t smem_u32(const void* p) {
    uint32_t a;
    asm("{ .reg .u64 t; cvta.to.shared.u64 t, %1; cvt.u32.u64 %0, t; }" : "=r"(a) : "l"(p));
    return a;
}
__device__ __forceinline__ uint32_t f2tf32(float x) {
    uint32_t r;
    asm("cvt.rna.tf32.f32 %0, %1;" : "=r"(r) : "f"(x));
    return r;
}
__device__ __forceinline__ void mma_tf32(float d[4], const uint32_t a[4], const uint32_t b[2]) {
    asm volatile(
        "mma.sync.aligned.m16n8k8.row.col.f32.tf32.tf32.f32 "
        "{%0,%1,%2,%3}, {%4,%5,%6,%7}, {%8,%9}, {%0,%1,%2,%3};"
        : "+f"(d[0]), "+f"(d[1]), "+f"(d[2]), "+f"(d[3])
        : "r"(a[0]), "r"(a[1]), "r"(a[2]), "r"(a[3]), "r"(b[0]), "r"(b[1]));
}
#define CP_ASYNC16(saddr, gptr) \
    asm volatile("cp.async.cg.shared.global [%0], [%1], 16;" :: "r"(saddr), "l"(gptr) : "memory")
#define CP_COMMIT() asm volatile("cp.async.commit_group;" ::: "memory")
#define CP_WAIT0()  asm volatile("cp.async.wait_group 0;" ::: "memory")
#define CP_WAIT1()  asm volatile("cp.async.wait_group 1;" ::: "memory")

// ---------------------------------------------------------------------------
// Pre-quantize fp32 -> tf32 bits (vectorized; n must be multiple of 4)
// ---------------------------------------------------------------------------
__global__ __launch_bounds__(256)
void quant_tf32_kernel(const float4* __restrict__ in, uint4* __restrict__ out, int n4)
{
    int i = blockIdx.x * 256 + threadIdx.x;
    if (i < n4) {
        float4 v = in[i];
        uint4 o;
        o.x = f2tf32(v.x); o.y = f2tf32(v.y);
        o.z = f2tf32(v.z); o.w = f2tf32(v.w);
        out[i] = o;
    }
}

// ---------------------------------------------------------------------------
// tf32 mma.sync GEMM on pre-quantized operands: C = A @ W + bias
// A, W are tf32 BIT arrays. No cvt in the hot loop.
// mode 0: row-major store. mode 1: head-transposed store into [B,H,S,Dh].
// ---------------------------------------------------------------------------
#define TBM 128
#define TBN 128
#define TBK 32
#define TST 3
#define TNIT (DD / TBK)                   // 64
#define TSTAGE_F 8192                     // A 128*32 + B 32*128 words
#define TSMEM_BYTES (TST * TSTAGE_F * 4)  // 98304

__device__ __forceinline__ void gemm_load_stage(
    uint32_t* sm, int s, int it, int tid,
    const uint32_t* __restrict__ Ab, const uint32_t* __restrict__ W, int bn)
{
    uint32_t* As = sm + s * TSTAGE_F;
    uint32_t* Bs = As + 4096;
    const int k0 = it * TBK;
#pragma unroll
    for (int j = 0; j < 8; j++) {
        int idx = j * 128 + tid;
        int row = idx >> 3;
        int c4  = (idx & 7) * 4;
        uint32_t dst = smem_u32(As + row * 32 + (c4 ^ ((row & 7) * 4)));
        CP_ASYNC16(dst, Ab + (size_t)row * DD + k0 + c4);
    }
#pragma unroll
    for (int j = 0; j < 8; j++) {
        int idx = j * 128 + tid;
        int krow = idx >> 5;
        int n4   = (idx & 31) * 4;
        uint32_t dst = smem_u32(Bs + krow * 128 + (n4 ^ ((krow & 3) * 8)));
        CP_ASYNC16(dst, W + (size_t)(k0 + krow) * DD + bn + n4);
    }
}

__global__ __launch_bounds__(128, 2)
void gemm_tf32(const uint32_t* __restrict__ A, const uint32_t* __restrict__ W,
               const float* __restrict__ bias, float* __restrict__ C, int mode)
{
    extern __shared__ uint32_t smu[];
    const int tid  = threadIdx.x;
    const int wid  = tid >> 5;
    const int lane = tid & 31;
    const int gid  = lane >> 2;
    const int tig  = lane & 3;
    const int wm   = wid >> 1;
    const int wn   = wid & 1;
    const int bm = blockIdx.y * TBM;
    const int bn = blockIdx.x * TBN;

    float acc[4][8][4];
#pragma unroll
    for (int i = 0; i < 4; i++)
#pragma unroll
        for (int j = 0; j < 8; j++)
#pragma unroll
            for (int c = 0; c < 4; c++) acc[i][j][c] = 0.f;

    const uint32_t* Ab = A + (size_t)bm * DD;

    gemm_load_stage(smu, 0, 0, tid, Ab, W, bn); CP_COMMIT();
    gemm_load_stage(smu, 1, 1, tid, Ab, W, bn); CP_COMMIT();

    for (int it = 0; it < TNIT; it++) {
        CP_WAIT1();
        __syncthreads();
        if (it + TST - 1 < TNIT)
            gemm_load_stage(smu, (it + TST - 1) % TST, it + TST - 1, tid, Ab, W, bn);
        CP_COMMIT();

        const uint32_t* As = smu + (it % TST) * TSTAGE_F;
        const uint32_t* Bs = As + 4096;
        const int abase = (wm * 64 + gid) * 32;
        const int axor  = gid * 4;

#pragma unroll
        for (int ks = 0; ks < 4; ks++) {
            const int kk  = ks * 8 + tig;
            const int kx0 = kk ^ axor;
            const int kx4 = (kk + 4) ^ axor;

            uint32_t af[4][4];
#pragma unroll
            for (int mf = 0; mf < 4; mf++) {
                const int r0 = abase + mf * 16 * 32;
                af[mf][0] = As[r0 + kx0];
                af[mf][1] = As[r0 + 8 * 32 + kx0];
                af[mf][2] = As[r0 + kx4];
                af[mf][3] = As[r0 + 8 * 32 + kx4];
            }
            uint32_t bf[8][2];
            const int brow0 = kk * 128;
            const int brow1 = (kk + 4) * 128;
            const int nxor  = tig * 8;
#pragma unroll
            for (int nf = 0; nf < 8; nf++) {
                const int nc = wn * 64 + ((nf * 8 + gid) ^ nxor);
                bf[nf][0] = Bs[brow0 + nc];
                bf[nf][1] = Bs[brow1 + nc];
            }
#pragma unroll
            for (int mf = 0; mf < 4; mf++)
#pragma unroll
                for (int nf = 0; nf < 8; nf++)
                    mma_tf32(acc[mf][nf], af[mf], bf[nf]);
        }
        __syncthreads();
    }

#pragma unroll
    for (int mf = 0; mf < 4; mf++) {
#pragma unroll
        for (int half = 0; half < 2; half++) {
            const int row = bm + wm * 64 + mf * 16 + gid + half * 8;
            float* dst;
            if (mode == 0) {
                dst = C + (size_t)row * DD + bn;
            } else {
                int b_ = row >> 11;
                int s_ = row & (SS - 1);
                int h_ = bn >> 7;
                dst = C + ((size_t)((b_ * HH + h_) * SS) + s_) * DH;
            }
#pragma unroll
            for (int nf = 0; nf < 8; nf++) {
                const int cl = wn * 64 + nf * 8 + tig * 2;
                float2 bv = *(const float2*)(bias + bn + cl);
                float2 v;
                v.x = acc[mf][nf][half * 2 + 0] + bv.x;
                v.y = acc[mf][nf][half * 2 + 1] + bv.y;
                *(float2*)(dst + cl) = v;
            }
        }
    }
}

// ---------------------------------------------------------------------------
// Tensor-core causal flash attention on pre-quantized K/V bits.
// CTA: 128 q-rows x full head. 8 warps, each owns 16 q-rows.
// No cvt in QK^T or PV inner loops (K/V/P all tf32 bits in smem).
// ---------------------------------------------------------------------------
#define AQ 128
#define AKV 64
#define KS_STR 132
#define VS_STR 136
#define PS_STR 68
#define A2_KS_F (2 * AKV * KS_STR)      // 16896 words
#define A2_VS_F (2 * AKV * VS_STR)      // 17408
#define A2_PS_F (AQ * PS_STR)           // 8704
#define A2_SMEM_BYTES ((A2_KS_F + A2_VS_F + A2_PS_F) * 4)   // 172032

__device__ __forceinline__ void attn_load_kv(
    uint32_t* Ks, uint32_t* Vs, int stage, int kb, int tid,
    const uint32_t* __restrict__ Kbh, const uint32_t* __restrict__ Vbh)
{
    const uint32_t* Kb = Kbh + (size_t)kb * AKV * DH;
    const uint32_t* Vb = Vbh + (size_t)kb * AKV * DH;
    uint32_t* Kd = Ks + stage * AKV * KS_STR;
    uint32_t* Vd = Vs + stage * AKV * VS_STR;
#pragma unroll
    for (int j = 0; j < 8; j++) {
        int idx = j * 256 + tid;
        int row = idx >> 5;
        int c4  = (idx & 31) * 4;
        CP_ASYNC16(smem_u32(Kd + row * KS_STR + c4), Kb + (size_t)row * DH + c4);
    }
#pragma unroll
    for (int j = 0; j < 8; j++) {
        int idx = j * 256 + tid;
        int row = idx >> 5;
        int c4  = (idx & 31) * 4;
        CP_ASYNC16(smem_u32(Vd + row * VS_STR + c4), Vb + (size_t)row * DH + c4);
    }
}

__global__ __launch_bounds__(256, 1)
void attn_tc(const float* __restrict__ Q, const uint32_t* __restrict__ K,
             const uint32_t* __restrict__ V, float* __restrict__ ctxout)
{
    extern __shared__ uint32_t smw[];
    uint32_t* Ks = smw;
    uint32_t* Vs = smw + A2_KS_F;
    uint32_t* Ps = Vs + A2_VS_F;

    const int qb = blockIdx.x;
    const int h  = blockIdx.y;
    const int b  = blockIdx.z;
    const int tid = threadIdx.x;
    const int w   = tid >> 5;
    const int lane = tid & 31;
    const int g = lane >> 2;
    const int t = lane & 3;

    const float* Qbase = Q + (size_t)(b * SS + qb * AQ) * DD + h * DH;
    const uint32_t* Kbh = K + (size_t)((b * HH + h) * SS) * DH;
    const uint32_t* Vbh = V + (size_t)((b * HH + h) * SS) * DH;

    // ---- stage Q tile (fp32 bits) into Ks area, coalesced ----
#pragma unroll
    for (int j = 0; j < 16; j++) {
        int idx = j * 256 + tid;
        int row = idx >> 5;
        int c4  = (idx & 31) * 4;
        CP_ASYNC16(smem_u32(Ks + row * KS_STR + c4), Qbase + (size_t)row * DD + c4);
    }
    CP_COMMIT();
    CP_WAIT0();
    __syncthreads();

    // ---- Q fragments (scaled, cvt once) held in registers for whole CTA ----
    uint32_t qf[16][4];
    {
        const float scale = 0.08838834764831845f;   // 1/sqrt(128)
        const uint32_t* qr0 = Ks + (w * 16 + g) * KS_STR;
        const uint32_t* qr1 = qr0 + 8 * KS_STR;
#pragma unroll
        for (int kk = 0; kk < 16; kk++) {
            qf[kk][0] = f2tf32(__uint_as_float(qr0[kk * 8 + t]) * scale);
            qf[kk][1] = f2tf32(__uint_as_float(qr1[kk * 8 + t]) * scale);
            qf[kk][2] = f2tf32(__uint_as_float(qr0[kk * 8 + t + 4]) * scale);
            qf[kk][3] = f2tf32(__uint_as_float(qr1[kk * 8 + t + 4]) * scale);
        }
    }
    __syncthreads();

    float ctx[16][4];
#pragma unroll
    for (int i = 0; i < 16; i++)
#pragma unroll
        for (int c = 0; c < 4; c++) ctx[i][c] = 0.f;
    float m0 = -INFINITY, m1 = -INFINITY, l0 = 0.f, l1 = 0.f;

    const int nkb = 2 * qb + 2;
    const int qrow0 = qb * AQ + w * 16 + g;
    uint32_t* Pw = Ps + (w * 16 + g) * PS_STR;
    const uint32_t* Pr0 = Ps + (w * 16 + g) * PS_STR;
    const uint32_t* Pr1 = Pr0 + 8 * PS_STR;

    attn_load_kv(Ks, Vs, 0, 0, tid, Kbh, Vbh);
    CP_COMMIT();

    for (int kb = 0; kb < nkb; kb++) {
        if (kb + 1 < nkb) {
            attn_load_kv(Ks, Vs, (kb + 1) & 1, kb + 1, tid, Kbh, Vbh);
            CP_COMMIT();
            CP_WAIT1();
        } else {
            CP_WAIT0();
        }
        __syncthreads();

        const bool skip = (kb * AKV > qb * AQ + w * 16 + 15);
        if (!skip) {
            const uint32_t* Kst = Ks + (kb & 1) * AKV * KS_STR;
            const uint32_t* Vst = Vs + (kb & 1) * AKV * VS_STR;

            // ---- S = Q K^T : bits-direct, no cvt ----
            float sf[8][4];
#pragma unroll
            for (int nf = 0; nf < 8; nf++)
#pragma unroll
                for (int c = 0; c < 4; c++) sf[nf][c] = 0.f;

#pragma unroll
            for (int kk = 0; kk < 16; kk++) {
#pragma unroll
                for (int nf = 0; nf < 8; nf++) {
                    uint32_t bf[2];
                    const uint32_t* kp = Kst + (nf * 8 + g) * KS_STR + kk * 8 + t;
                    bf[0] = kp[0];
                    bf[1] = kp[4];
                    mma_tf32(sf[nf], qf[kk], bf);
                }
            }

            // ---- causal mask (only near diagonal) ----
            if (kb * AKV + 63 > qb * AQ + w * 16) {
#pragma unroll
                for (int nf = 0; nf < 8; nf++) {
                    int kv = kb * AKV + nf * 8 + 2 * t;
                    if (kv     > qrow0)     sf[nf][0] = -1e30f;
                    if (kv + 1 > qrow0)     sf[nf][1] = -1e30f;
                    if (kv     > qrow0 + 8) sf[nf][2] = -1e30f;
                    if (kv + 1 > qrow0 + 8) sf[nf][3] = -1e30f;
                }
            }

            // ---- online softmax (rows qrow0, qrow0+8) ----
            float rm0 = -1e30f, rm1 = -1e30f;
#pragma unroll
            for (int nf = 0; nf < 8; nf++) {
                rm0 = fmaxf(rm0, fmaxf(sf[nf][0], sf[nf][1]));
                rm1 = fmaxf(rm1, fmaxf(sf[nf][2], sf[nf][3]));
            }
            rm0 = fmaxf(rm0, __shfl_xor_sync(0xffffffffu, rm0, 1));
            rm0 = fmaxf(rm0, __shfl_xor_sync(0xffffffffu, rm0, 2));
            rm1 = fmaxf(rm1, __shfl_xor_sync(0xffffffffu, rm1, 1));
            rm1 = fmaxf(rm1, __shfl_xor_sync(0xffffffffu, rm1, 2));

            float mn0 = fmaxf(m0, rm0), mn1 = fmaxf(m1, rm1);
            float al0 = __expf(m0 - mn0), al1 = __expf(m1 - mn1);
            float s0 = 0.f, s1 = 0.f;

#pragma unroll
            for (int nf = 0; nf < 8; nf++) {
                float p0 = __expf(sf[nf][0] - mn0);
                float p1 = __expf(sf[nf][1] - mn0);
                float p2 = __expf(sf[nf][2] - mn1);
                float p3 = __expf(sf[nf][3] - mn1);
                s0 += p0 + p1;
                s1 += p2 + p3;
                uint2 v0 = make_uint2(f2tf32(p0), f2tf32(p1));
                uint2 v1 = make_uint2(f2tf32(p2), f2tf32(p3));
                *(uint2*)(Pw + nf * 8 + 2 * t)              = v0;
                *(uint2*)(Pw + 8 * PS_STR + nf * 8 + 2 * t) = v1;
            }
            s0 += __shfl_xor_sync(0xffffffffu, s0, 1);
            s0 += __shfl_xor_sync(0xffffffffu, s0, 2);
            s1 += __shfl_xor_sync(0xffffffffu, s1, 1);
            s1 += __shfl_xor_sync(0xffffffffu, s1, 2);
            l0 = l0 * al0 + s0;
            l1 = l1 * al1 + s1;
            m0 = mn0; m1 = mn1;

#pragma unroll
            for (int nf = 0; nf < 16; nf++) {
                ctx[nf][0] *= al0; ctx[nf][1] *= al0;
                ctx[nf][2] *= al1; ctx[nf][3] *= al1;
            }
            __syncwarp();

            // ---- ctx += P @ V : bits-direct, no cvt ----
#pragma unroll
            for (int kk = 0; kk < 8; kk++) {
                uint32_t af[4];
                af[0] = Pr0[kk * 8 + t];
                af[1] = Pr1[kk * 8 + t];
                af[2] = Pr0[kk * 8 + t + 4];
                af[3] = Pr1[kk * 8 + t + 4];
#pragma unroll
                for (int nf = 0; nf < 16; nf++) {
                    uint32_t bf[2];
                    const uint32_t* vp = Vst + (kk * 8 + t) * VS_STR + nf * 8 + g;
                    bf[0] = vp[0];
                    bf[1] = vp[4 * VS_STR];
                    mma_tf32(ctx[nf], af, bf);
                }
            }
        }
        __syncthreads();
    }

    // ---- epilogue: normalize, write to [B*S, D] ----
    const float inv0 = 1.f / l0;
    const float inv1 = 1.f / l1;
    float* d0 = ctxout + (size_t)(b * SS + qrow0) * DD + h * DH;
    float* d1 = d0 + (size_t)8 * DD;
#pragma unroll
    for (int nf = 0; nf < 16; nf++) {
        float2 v0 = make_float2(ctx[nf][0] * inv0, ctx[nf][1] * inv0);
        float2 v1 = make_float2(ctx[nf][2] * inv1, ctx[nf][3] * inv1);
        *(float2*)(d0 + nf * 8 + 2 * t) = v0;
        *(float2*)(d1 + nf * 8 + 2 * t) = v1;
    }
}

// ---------------------------------------------------------------------------
// Residual add + LayerNorm (unchanged)
// ---------------------------------------------------------------------------
__global__ __launch_bounds__(256)
void mhsa_add_ln_kernel(const float* __restrict__ x, const float* __restrict__ ao,
                        const float* __restrict__ gamma, const float* __restrict__ beta,
                        float* __restrict__ ln)
{
    const int row = blockIdx.x;
    const int tid = threadIdx.x;
    const float4* xr = (const float4*)(x + (size_t)row * DD);
    const float4* ar = (const float4*)(ao + (size_t)row * DD);

    float4 y0, y1;
    {
        float4 xv = xr[tid], av = ar[tid];
        y0 = make_float4(xv.x + av.x, xv.y + av.y, xv.z + av.z, xv.w + av.w);
        xv = xr[tid + 256]; av = ar[tid + 256];
        y1 = make_float4(xv.x + av.x, xv.y + av.y, xv.z + av.z, xv.w + av.w);
    }
    float s  = y0.x + y0.y + y0.z + y0.w + y1.x + y1.y + y1.z + y1.w;
    float sq = y0.x*y0.x + y0.y*y0.y + y0.z*y0.z + y0.w*y0.w
             + y1.x*y1.x + y1.y*y1.y + y1.z*y1.z + y1.w*y1.w;

#pragma unroll
    for (int off = 16; off; off >>= 1) {
        s  += __shfl_xor_sync(0xffffffffu, s,  off);
        sq += __shfl_xor_sync(0xffffffffu, sq, off);
    }
    __shared__ float shs[8], shq[8];
    __shared__ float stats[2];
    int w = tid >> 5, lane = tid & 31;
    if (lane == 0) { shs[w] = s; shq[w] = sq; }
    __syncthreads();
    if (tid == 0) {
        float ts = 0.f, tq = 0.f;
#pragma unroll
        for (int i = 0; i < 8; i++) { ts += shs[i]; tq += shq[i]; }
        float mu = ts / (float)DD;
        float var = tq / (float)DD - mu * mu;
        stats[0] = mu;
        stats[1] = rsqrtf(var + 1e-5f);
    }
    __syncthreads();
    float mu = stats[0], rinv = stats[1];

    const float4* g4 = (const float4*)gamma;
    const float4* b4 = (const float4*)beta;
    float4* lr = (float4*)(ln + (size_t)row * DD);
    {
        float4 gv = g4[tid], bv = b4[tid];
        float4 o = make_float4(gv.x * (y0.x - mu) * rinv + bv.x,
                               gv.y * (y0.y - mu) * rinv + bv.y,
                               gv.z * (y0.z - mu) * rinv + bv.z,
                               gv.w * (y0.w - mu) * rinv + bv.w);
        lr[tid] = o;
        gv = g4[tid + 256]; bv = b4[tid + 256];
        o = make_float4(gv.x * (y1.x - mu) * rinv + bv.x,
                        gv.y * (y1.y - mu) * rinv + bv.y,
                        gv.z * (y1.z - mu) * rinv + bv.z,
                        gv.w * (y1.w - mu) * rinv + bv.w);
        lr[tid + 256] = o;
    }
}

// ---------------------------------------------------------------------------
// Launch. Inputs: x, Wq, bq, Wk, bk, Wv, bv, Wo, bo, gamma, beta, num_heads.
// Output tuple (ln, attn_out, k, v) flattened into d_out.
// ---------------------------------------------------------------------------
extern "C" void kernel_launch(void* const* d_in, const int* in_sizes, int n_in,
                              void* d_out, int out_size)
{
    const float* x     = (const float*)d_in[0];
    const float* Wq    = (const float*)d_in[1];
    const float* bq    = (const float*)d_in[2];
    const float* Wk    = (const float*)d_in[3];
    const float* bk    = (const float*)d_in[4];
    const float* Wv    = (const float*)d_in[5];
    const float* bv    = (const float*)d_in[6];
    const float* Wo    = (const float*)d_in[7];
    const float* bo    = (const float*)d_in[8];
    const float* gamma = (const float*)d_in[9];
    const float* beta  = (const float*)d_in[10];

    float* out      = (float*)d_out;
    const size_t SEC = (size_t)BB * SS * DD;   // 8388608
    float* out_ln   = out;
    float* out_ao   = out + SEC;
    float* out_k    = out + 2 * SEC;
    float* out_v    = out + 3 * SEC;

    float *qptr = nullptr, *cptr = nullptr;
    uint32_t *xq = nullptr, *wq = nullptr, *kq = nullptr, *vq = nullptr, *cq = nullptr;
    cudaGetSymbolAddress((void**)&qptr, g_Q);
    cudaGetSymbolAddress((void**)&cptr, g_ctx);
    cudaGetSymbolAddress((void**)&xq,   g_xq);
    cudaGetSymbolAddress((void**)&wq,   g_wq);
    cudaGetSymbolAddress((void**)&kq,   g_kq);
    cudaGetSymbolAddress((void**)&vq,   g_vq);
    cudaGetSymbolAddress((void**)&cq,   g_cq);
    uint32_t* wqq = wq;
    uint32_t* wkq = wq + (size_t)DD * DD;
    uint32_t* wvq = wq + 2ull * DD * DD;
    uint32_t* woq = wq + 3ull * DD * DD;

    cudaFuncSetAttribute(attn_tc,
                         cudaFuncAttributeMaxDynamicSharedMemorySize, A2_SMEM_BYTES);
    cudaFuncSetAttribute(gemm_tf32,
                         cudaFuncAttributeMaxDynamicSharedMemorySize, TSMEM_BYTES);

    const int NX4 = MM * DD / 4;        // 2,097,152
    const int NW4 = DD * DD / 4;        // 1,048,576

    // ---- pre-quantize x and weights to tf32 bits ----
    quant_tf32_kernel<<<NX4 / 256, 256>>>((const float4*)x,  (uint4*)xq,  NX4);
    quant_tf32_kernel<<<NW4 / 256, 256>>>((const float4*)Wq, (uint4*)wqq, NW4);
    quant_tf32_kernel<<<NW4 / 256, 256>>>((const float4*)Wk, (uint4*)wkq, NW4);
    quant_tf32_kernel<<<NW4 / 256, 256>>>((const float4*)Wv, (uint4*)wvq, NW4);
    quant_tf32_kernel<<<NW4 / 256, 256>>>((const float4*)Wo, (uint4*)woq, NW4);

    dim3 ggrid(DD / TBN, MM / TBM);   // (16, 32)

    // Projections: Q -> scratch (row-major), K/V -> output slots ([B,H,S,Dh])
    gemm_tf32<<<ggrid, 128, TSMEM_BYTES>>>(xq, wqq, bq, qptr, 0);
    gemm_tf32<<<ggrid, 128, TSMEM_BYTES>>>(xq, wkq, bk, out_k, 1);
    gemm_tf32<<<ggrid, 128, TSMEM_BYTES>>>(xq, wvq, bv, out_v, 1);

    // pre-quantize K/V for attention (bit-identical to in-loop cvt before)
    quant_tf32_kernel<<<NX4 / 256, 256>>>((const float4*)out_k, (uint4*)kq, NX4);
    quant_tf32_kernel<<<NX4 / 256, 256>>>((const float4*)out_v, (uint4*)vq, NX4);

    // Tensor-core flash attention
    dim3 agrid(SS / AQ, HH, BB);      // (16, 16, 2)
    attn_tc<<<agrid, 256, A2_SMEM_BYTES>>>(qptr, kq, vq, cptr);

    // pre-quantize ctx, then output projection
    quant_tf32_kernel<<<NX4 / 256, 256>>>((const float4*)cptr, (uint4*)cq, NX4);
    gemm_tf32<<<ggrid, 128, TSMEM_BYTES>>>(cq, woq, bo, out_ao, 0);

    // Residual + LayerNorm
    mhsa_add_ln_kernel<<<MM, 256>>>(x, out_ao, gamma, beta, out_ln);
}

// round 10
// speedup vs baseline: 4.1552x; 1.0896x over previous
#include <cuda_runtime.h>
#include <cuda_bf16.h>
#include <math.h>
#include <stdint.h>

// Problem constants: B=2, S=2048, D=2048, H=16, Dh=128
#define BB 2
#define SS 2048
#define DD 2048
#define HH 16
#define DH 128
#define MM (BB*SS)          // 4096 rows for the projection GEMMs

// ---------------------------------------------------------------------------
// Scratch (device globals — allocation-free per harness rules)
// ---------------------------------------------------------------------------
__device__ float    g_Q[BB*SS*DD];      // Q projection (fp32)
__device__ float    g_ctx[BB*SS*DD];    // attention context (fp32)
__device__ uint32_t g_xq[MM*DD];        // x, tf32 bits
__device__ uint32_t g_wq[4ull*DD*DD];   // Wq,Wk,Wv,Wo, tf32 bits
__device__ uint32_t g_kq[BB*SS*DD];     // k, tf32 bits ([B,H,S,Dh])
__device__ uint32_t g_vq[BB*SS*DD];     // v, tf32 bits
__device__ uint32_t g_cq[BB*SS*DD];     // ctx, tf32 bits

// ---------------------------------------------------------------------------
// PTX helpers (family-portable: mma.sync + cp.async only — NO tcgen05, the
// harness compiles via compute_103 base target which rejects "a" features)
// ---------------------------------------------------------------------------
__device__ __forceinline__ uint32_t smem_u32(const void* p) {
    uint32_t a;
    asm("{ .reg .u64 t; cvta.to.shared.u64 t, %1; cvt.u32.u64 %0, t; }" : "=r"(a) : "l"(p));
    return a;
}
__device__ __forceinline__ uint32_t f2tf32(float x) {
    uint32_t r;
    asm("cvt.rna.tf32.f32 %0, %1;" : "=r"(r) : "f"(x));
    return r;
}
__device__ __forceinline__ void mma_tf32(float d[4], const uint32_t a[4], const uint32_t b[2]) {
    asm volatile(
        "mma.sync.aligned.m16n8k8.row.col.f32.tf32.tf32.f32 "
        "{%0,%1,%2,%3}, {%4,%5,%6,%7}, {%8,%9}, {%0,%1,%2,%3};"
        : "+f"(d[0]), "+f"(d[1]), "+f"(d[2]), "+f"(d[3])
        : "r"(a[0]), "r"(a[1]), "r"(a[2]), "r"(a[3]), "r"(b[0]), "r"(b[1]));
}
#define CP_ASYNC16(saddr, gptr) \
    asm volatile("cp.async.cg.shared.global [%0], [%1], 16;" :: "r"(saddr), "l"(gptr) : "memory")
#define CP_COMMIT() asm volatile("cp.async.commit_group;" ::: "memory")
#define CP_WAIT0()  asm volatile("cp.async.wait_group 0;" ::: "memory")
#define CP_WAIT1()  asm volatile("cp.async.wait_group 1;" ::: "memory")

// ---------------------------------------------------------------------------
// One-shot pre-quantization: x (NX4 uint4) + Wq,Wk,Wv,Wo (NW4 uint4 each)
// ---------------------------------------------------------------------------
#define NX4 (MM * DD / 4)        // 2,097,152
#define NW4 (DD * DD / 4)        // 1,048,576  (= 1 << 20)
#define QA_BLOCKS ((NX4 + 4 * NW4) / 256)   // 24576

__device__ __forceinline__ uint4 quant4(float4 v) {
    uint4 o;
    o.x = f2tf32(v.x); o.y = f2tf32(v.y);
    o.z = f2tf32(v.z); o.w = f2tf32(v.w);
    return o;
}

__global__ __launch_bounds__(256)
void quant_all_kernel(const float4* __restrict__ x,
                      const float4* __restrict__ w0, const float4* __restrict__ w1,
                      const float4* __restrict__ w2, const float4* __restrict__ w3,
                      uint4* __restrict__ xq, uint4* __restrict__ wq)
{
    int i = blockIdx.x * 256 + threadIdx.x;
    if (i < NX4) {
        xq[i] = quant4(x[i]);
    } else {
        int k = i - NX4;
        int seg = k >> 20;                 // NW4 == 1<<20
        int j   = k & (NW4 - 1);
        const float4* src = (seg == 0) ? w0 : (seg == 1) ? w1 : (seg == 2) ? w2 : w3;
        wq[(size_t)seg * NW4 + j] = quant4(src[j]);
    }
}

// ---------------------------------------------------------------------------
// tf32 mma.sync GEMM core on pre-quantized operands: C = A @ W + bias
// mode 0: row-major store. mode 1: head-transposed store into [B,H,S,Dh].
// Cq (optional): mirror store of tf32 bits at the same offsets.
// ---------------------------------------------------------------------------
#define TBM 128
#define TBN 128
#define TBK 32
#define TST 3
#define TNIT (DD / TBK)                   // 64
#define TSTAGE_F 8192                     // A 128*32 + B 32*128 words
#define TSMEM_BYTES (TST * TSTAGE_F * 4)  // 98304

__device__ __forceinline__ void gemm_load_stage(
    uint32_t* sm, int s, int it, int tid,
    const uint32_t* __restrict__ Ab, const uint32_t* __restrict__ W, int bn)
{
    uint32_t* As = sm + s * TSTAGE_F;
    uint32_t* Bs = As + 4096;
    const int k0 = it * TBK;
#pragma unroll
    for (int j = 0; j < 8; j++) {
        int idx = j * 128 + tid;
        int row = idx >> 3;
        int c4  = (idx & 7) * 4;
        uint32_t dst = smem_u32(As + row * 32 + (c4 ^ ((row & 7) * 4)));
        CP_ASYNC16(dst, Ab + (size_t)row * DD + k0 + c4);
    }
#pragma unroll
    for (int j = 0; j < 8; j++) {
        int idx = j * 128 + tid;
        int krow = idx >> 5;
        int n4   = (idx & 31) * 4;
        uint32_t dst = smem_u32(Bs + krow * 128 + (n4 ^ ((krow & 3) * 8)));
        CP_ASYNC16(dst, W + (size_t)(k0 + krow) * DD + bn + n4);
    }
}

__device__ __forceinline__ void gemm_core(
    uint32_t* smu,
    const uint32_t* __restrict__ A, const uint32_t* __restrict__ W,
    const float* __restrict__ bias, float* __restrict__ C,
    uint32_t* __restrict__ Cq, int mode, int bm, int bn)
{
    const int tid  = threadIdx.x;
    const int wid  = tid >> 5;
    const int lane = tid & 31;
    const int gid  = lane >> 2;
    const int tig  = lane & 3;
    const int wm   = wid >> 1;
    const int wn   = wid & 1;

    float acc[4][8][4];
#pragma unroll
    for (int i = 0; i < 4; i++)
#pragma unroll
        for (int j = 0; j < 8; j++)
#pragma unroll
            for (int c = 0; c < 4; c++) acc[i][j][c] = 0.f;

    const uint32_t* Ab = A + (size_t)bm * DD;

    gemm_load_stage(smu, 0, 0, tid, Ab, W, bn); CP_COMMIT();
    gemm_load_stage(smu, 1, 1, tid, Ab, W, bn); CP_COMMIT();

    for (int it = 0; it < TNIT; it++) {
        CP_WAIT1();
        __syncthreads();
        if (it + TST - 1 < TNIT)
            gemm_load_stage(smu, (it + TST - 1) % TST, it + TST - 1, tid, Ab, W, bn);
        CP_COMMIT();

        const uint32_t* As = smu + (it % TST) * TSTAGE_F;
        const uint32_t* Bs = As + 4096;
        const int abase = (wm * 64 + gid) * 32;
        const int axor  = gid * 4;

#pragma unroll
        for (int ks = 0; ks < 4; ks++) {
            const int kk  = ks * 8 + tig;
            const int kx0 = kk ^ axor;
            const int kx4 = (kk + 4) ^ axor;

            uint32_t af[4][4];
#pragma unroll
            for (int mf = 0; mf < 4; mf++) {
                const int r0 = abase + mf * 16 * 32;
                af[mf][0] = As[r0 + kx0];
                af[mf][1] = As[r0 + 8 * 32 + kx0];
                af[mf][2] = As[r0 + kx4];
                af[mf][3] = As[r0 + 8 * 32 + kx4];
            }
            uint32_t bf[8][2];
            const int brow0 = kk * 128;
            const int brow1 = (kk + 4) * 128;
            const int nxor  = tig * 8;
#pragma unroll
            for (int nf = 0; nf < 8; nf++) {
                const int nc = wn * 64 + ((nf * 8 + gid) ^ nxor);
                bf[nf][0] = Bs[brow0 + nc];
                bf[nf][1] = Bs[brow1 + nc];
            }
#pragma unroll
            for (int mf = 0; mf < 4; mf++)
#pragma unroll
                for (int nf = 0; nf < 8; nf++)
                    mma_tf32(acc[mf][nf], af[mf], bf[nf]);
        }
        __syncthreads();
    }

#pragma unroll
    for (int mf = 0; mf < 4; mf++) {
#pragma unroll
        for (int half = 0; half < 2; half++) {
            const int row = bm + wm * 64 + mf * 16 + gid + half * 8;
            size_t off;
            if (mode == 0) {
                off = (size_t)row * DD + bn;
            } else {
                int b_ = row >> 11;
                int s_ = row & (SS - 1);
                int h_ = bn >> 7;
                off = ((size_t)((b_ * HH + h_) * SS) + s_) * DH;
            }
            float* dst = C + off;
#pragma unroll
            for (int nf = 0; nf < 8; nf++) {
                const int cl = wn * 64 + nf * 8 + tig * 2;
                float2 bv = *(const float2*)(bias + bn + cl);
                float2 v;
                v.x = acc[mf][nf][half * 2 + 0] + bv.x;
                v.y = acc[mf][nf][half * 2 + 1] + bv.y;
                *(float2*)(dst + cl) = v;
                if (Cq) {
                    uint2 qv = make_uint2(f2tf32(v.x), f2tf32(v.y));
                    *(uint2*)(Cq + off + cl) = qv;
                }
            }
        }
    }
}

// Merged Q/K/V projection: blockIdx.z selects the GEMM. K/V also emit tf32 bits.
__global__ __launch_bounds__(128, 2)
void gemm_qkv(const uint32_t* __restrict__ A,
              const uint32_t* __restrict__ W0, const uint32_t* __restrict__ W1,
              const uint32_t* __restrict__ W2,
              const float* __restrict__ b0, const float* __restrict__ b1,
              const float* __restrict__ b2,
              float* __restrict__ C0, float* __restrict__ C1, float* __restrict__ C2,
              uint32_t* __restrict__ kq, uint32_t* __restrict__ vq)
{
    extern __shared__ uint32_t smu[];
    const int z = blockIdx.z;
    const uint32_t* W = (z == 0) ? W0 : (z == 1) ? W1 : W2;
    const float* bias = (z == 0) ? b0 : (z == 1) ? b1 : b2;
    float* C          = (z == 0) ? C0 : (z == 1) ? C1 : C2;
    uint32_t* Cq      = (z == 1) ? kq : (z == 2) ? vq : nullptr;
    gemm_core(smu, A, W, bias, C, Cq, (z > 0) ? 1 : 0,
              blockIdx.y * TBM, blockIdx.x * TBN);
}

// Output projection (row-major, no quant mirror)
__global__ __launch_bounds__(128, 2)
void gemm_o(const uint32_t* __restrict__ A, const uint32_t* __restrict__ W,
            const float* __restrict__ bias, float* __restrict__ C)
{
    extern __shared__ uint32_t smu[];
    gemm_core(smu, A, W, bias, C, nullptr, 0, blockIdx.y * TBM, blockIdx.x * TBN);
}

// ---------------------------------------------------------------------------
// Tensor-core causal flash attention on pre-quantized K/V bits.
// LPT: qb reversed vs blockIdx.x so longest CTAs launch first.
// Epilogue also emits ctx as tf32 bits (feeds gemm_o directly).
// ---------------------------------------------------------------------------
#define AQ 128
#define AKV 64
#define KS_STR 132
#define VS_STR 136
#define PS_STR 68
#define A2_KS_F (2 * AKV * KS_STR)      // 16896 words
#define A2_VS_F (2 * AKV * VS_STR)      // 17408
#define A2_PS_F (AQ * PS_STR)           // 8704
#define A2_SMEM_BYTES ((A2_KS_F + A2_VS_F + A2_PS_F) * 4)   // 172032

__device__ __forceinline__ void attn_load_kv(
    uint32_t* Ks, uint32_t* Vs, int stage, int kb, int tid,
    const uint32_t* __restrict__ Kbh, const uint32_t* __restrict__ Vbh)
{
    const uint32_t* Kb = Kbh + (size_t)kb * AKV * DH;
    const uint32_t* Vb = Vbh + (size_t)kb * AKV * DH;
    uint32_t* Kd = Ks + stage * AKV * KS_STR;
    uint32_t* Vd = Vs + stage * AKV * VS_STR;
#pragma unroll
    for (int j = 0; j < 8; j++) {
        int idx = j * 256 + tid;
        int row = idx >> 5;
        int c4  = (idx & 31) * 4;
        CP_ASYNC16(smem_u32(Kd + row * KS_STR + c4), Kb + (size_t)row * DH + c4);
    }
#pragma unroll
    for (int j = 0; j < 8; j++) {
        int idx = j * 256 + tid;
        int row = idx >> 5;
        int c4  = (idx & 31) * 4;
        CP_ASYNC16(smem_u32(Vd + row * VS_STR + c4), Vb + (size_t)row * DH + c4);
    }
}

__global__ __launch_bounds__(256, 1)
void attn_tc(const float* __restrict__ Q, const uint32_t* __restrict__ K,
             const uint32_t* __restrict__ V, float* __restrict__ ctxout,
             uint32_t* __restrict__ ctxq)
{
    extern __shared__ uint32_t smw[];
    uint32_t* Ks = smw;
    uint32_t* Vs = smw + A2_KS_F;
    uint32_t* Ps = Vs + A2_VS_F;

    const int qb = (gridDim.x - 1) - blockIdx.x;   // LPT: longest first
    const int h  = blockIdx.y;
    const int b  = blockIdx.z;
    const int tid = threadIdx.x;
    const int w   = tid >> 5;
    const int lane = tid & 31;
    const int g = lane >> 2;
    const int t = lane & 3;

    const float* Qbase = Q + (size_t)(b * SS + qb * AQ) * DD + h * DH;
    const uint32_t* Kbh = K + (size_t)((b * HH + h) * SS) * DH;
    const uint32_t* Vbh = V + (size_t)((b * HH + h) * SS) * DH;

    // ---- stage Q tile (fp32 bits) into Ks area, coalesced ----
#pragma unroll
    for (int j = 0; j < 16; j++) {
        int idx = j * 256 + tid;
        int row = idx >> 5;
        int c4  = (idx & 31) * 4;
        CP_ASYNC16(smem_u32(Ks + row * KS_STR + c4), Qbase + (size_t)row * DD + c4);
    }
    CP_COMMIT();
    CP_WAIT0();
    __syncthreads();

    // ---- Q fragments (scaled, cvt once) held in registers for whole CTA ----
    uint32_t qf[16][4];
    {
        const float scale = 0.08838834764831845f;   // 1/sqrt(128)
        const uint32_t* qr0 = Ks + (w * 16 + g) * KS_STR;
        const uint32_t* qr1 = qr0 + 8 * KS_STR;
#pragma unroll
        for (int kk = 0; kk < 16; kk++) {
            qf[kk][0] = f2tf32(__uint_as_float(qr0[kk * 8 + t]) * scale);
            qf[kk][1] = f2tf32(__uint_as_float(qr1[kk * 8 + t]) * scale);
            qf[kk][2] = f2tf32(__uint_as_float(qr0[kk * 8 + t + 4]) * scale);
            qf[kk][3] = f2tf32(__uint_as_float(qr1[kk * 8 + t + 4]) * scale);
        }
    }
    __syncthreads();

    float ctx[16][4];
#pragma unroll
    for (int i = 0; i < 16; i++)
#pragma unroll
        for (int c = 0; c < 4; c++) ctx[i][c] = 0.f;
    float m0 = -INFINITY, m1 = -INFINITY, l0 = 0.f, l1 = 0.f;

    const int nkb = 2 * qb + 2;
    const int qrow0 = qb * AQ + w * 16 + g;
    uint32_t* Pw = Ps + (w * 16 + g) * PS_STR;
    const uint32_t* Pr0 = Ps + (w * 16 + g) * PS_STR;
    const uint32_t* Pr1 = Pr0 + 8 * PS_STR;

    attn_load_kv(Ks, Vs, 0, 0, tid, Kbh, Vbh);
    CP_COMMIT();

    for (int kb = 0; kb < nkb; kb++) {
        if (kb + 1 < nkb) {
            attn_load_kv(Ks, Vs, (kb + 1) & 1, kb + 1, tid, Kbh, Vbh);
            CP_COMMIT();
            CP_WAIT1();
        } else {
            CP_WAIT0();
        }
        __syncthreads();

        const bool skip = (kb * AKV > qb * AQ + w * 16 + 15);
        if (!skip) {
            const uint32_t* Kst = Ks + (kb & 1) * AKV * KS_STR;
            const uint32_t* Vst = Vs + (kb & 1) * AKV * VS_STR;

            // ---- S = Q K^T : bits-direct ----
            float sf[8][4];
#pragma unroll
            for (int nf = 0; nf < 8; nf++)
#pragma unroll
                for (int c = 0; c < 4; c++) sf[nf][c] = 0.f;

#pragma unroll
            for (int kk = 0; kk < 16; kk++) {
#pragma unroll
                for (int nf = 0; nf < 8; nf++) {
                    uint32_t bf[2];
                    const uint32_t* kp = Kst + (nf * 8 + g) * KS_STR + kk * 8 + t;
                    bf[0] = kp[0];
                    bf[1] = kp[4];
                    mma_tf32(sf[nf], qf[kk], bf);
                }
            }

            // ---- causal mask (only near diagonal) ----
            if (kb * AKV + 63 > qb * AQ + w * 16) {
#pragma unroll
                for (int nf = 0; nf < 8; nf++) {
                    int kv = kb * AKV + nf * 8 + 2 * t;
                    if (kv     > qrow0)     sf[nf][0] = -1e30f;
                    if (kv + 1 > qrow0)     sf[nf][1] = -1e30f;
                    if (kv     > qrow0 + 8) sf[nf][2] = -1e30f;
                    if (kv + 1 > qrow0 + 8) sf[nf][3] = -1e30f;
                }
            }

            // ---- online softmax (rows qrow0, qrow0+8) ----
            float rm0 = -1e30f, rm1 = -1e30f;
#pragma unroll
            for (int nf = 0; nf < 8; nf++) {
                rm0 = fmaxf(rm0, fmaxf(sf[nf][0], sf[nf][1]));
                rm1 = fmaxf(rm1, fmaxf(sf[nf][2], sf[nf][3]));
            }
            rm0 = fmaxf(rm0, __shfl_xor_sync(0xffffffffu, rm0, 1));
            rm0 = fmaxf(rm0, __shfl_xor_sync(0xffffffffu, rm0, 2));
            rm1 = fmaxf(rm1, __shfl_xor_sync(0xffffffffu, rm1, 1));
            rm1 = fmaxf(rm1, __shfl_xor_sync(0xffffffffu, rm1, 2));

            float mn0 = fmaxf(m0, rm0), mn1 = fmaxf(m1, rm1);
            float al0 = __expf(m0 - mn0), al1 = __expf(m1 - mn1);
            float s0 = 0.f, s1 = 0.f;

#pragma unroll
            for (int nf = 0; nf < 8; nf++) {
                float p0 = __expf(sf[nf][0] - mn0);
                float p1 = __expf(sf[nf][1] - mn0);
                float p2 = __expf(sf[nf][2] - mn1);
                float p3 = __expf(sf[nf][3] - mn1);
                s0 += p0 + p1;
                s1 += p2 + p3;
                uint2 v0 = make_uint2(f2tf32(p0), f2tf32(p1));
                uint2 v1 = make_uint2(f2tf32(p2), f2tf32(p3));
                *(uint2*)(Pw + nf * 8 + 2 * t)              = v0;
                *(uint2*)(Pw + 8 * PS_STR + nf * 8 + 2 * t) = v1;
            }
            s0 += __shfl_xor_sync(0xffffffffu, s0, 1);
            s0 += __shfl_xor_sync(0xffffffffu, s0, 2);
            s1 += __shfl_xor_sync(0xffffffffu, s1, 1);
            s1 += __shfl_xor_sync(0xffffffffu, s1, 2);
            l0 = l0 * al0 + s0;
            l1 = l1 * al1 + s1;
            m0 = mn0; m1 = mn1;

#pragma unroll
            for (int nf = 0; nf < 16; nf++) {
                ctx[nf][0] *= al0; ctx[nf][1] *= al0;
                ctx[nf][2] *= al1; ctx[nf][3] *= al1;
            }
            __syncwarp();

            // ---- ctx += P @ V : bits-direct ----
#pragma unroll
            for (int kk = 0; kk < 8; kk++) {
                uint32_t af[4];
                af[0] = Pr0[kk * 8 + t];
                af[1] = Pr1[kk * 8 + t];
                af[2] = Pr0[kk * 8 + t + 4];
                af[3] = Pr1[kk * 8 + t + 4];
#pragma unroll
                for (int nf = 0; nf < 16; nf++) {
                    uint32_t bf[2];
                    const uint32_t* vp = Vst + (kk * 8 + t) * VS_STR + nf * 8 + g;
                    bf[0] = vp[0];
                    bf[1] = vp[4 * VS_STR];
                    mma_tf32(ctx[nf], af, bf);
                }
            }
        }
        __syncthreads();
    }

    // ---- epilogue: normalize, write fp32 ctx AND tf32 bits ----
    const float inv0 = 1.f / l0;
    const float inv1 = 1.f / l1;
    const size_t off0 = (size_t)(b * SS + qrow0) * DD + h * DH;
    const size_t off1 = off0 + (size_t)8 * DD;
    float* d0 = ctxout + off0;
    float* d1 = ctxout + off1;
    uint32_t* q0 = ctxq + off0;
    uint32_t* q1 = ctxq + off1;
#pragma unroll
    for (int nf = 0; nf < 16; nf++) {
        float2 v0 = make_float2(ctx[nf][0] * inv0, ctx[nf][1] * inv0);
        float2 v1 = make_float2(ctx[nf][2] * inv1, ctx[nf][3] * inv1);
        *(float2*)(d0 + nf * 8 + 2 * t) = v0;
        *(float2*)(d1 + nf * 8 + 2 * t) = v1;
        *(uint2*)(q0 + nf * 8 + 2 * t) = make_uint2(f2tf32(v0.x), f2tf32(v0.y));
        *(uint2*)(q1 + nf * 8 + 2 * t) = make_uint2(f2tf32(v1.x), f2tf32(v1.y));
    }
}

// ---------------------------------------------------------------------------
// Residual add + LayerNorm (unchanged)
// ---------------------------------------------------------------------------
__global__ __launch_bounds__(256)
void mhsa_add_ln_kernel(const float* __restrict__ x, const float* __restrict__ ao,
                        const float* __restrict__ gamma, const float* __restrict__ beta,
                        float* __restrict__ ln)
{
    const int row = blockIdx.x;
    const int tid = threadIdx.x;
    const float4* xr = (const float4*)(x + (size_t)row * DD);
    const float4* ar = (const float4*)(ao + (size_t)row * DD);

    float4 y0, y1;
    {
        float4 xv = xr[tid], av = ar[tid];
        y0 = make_float4(xv.x + av.x, xv.y + av.y, xv.z + av.z, xv.w + av.w);
        xv = xr[tid + 256]; av = ar[tid + 256];
        y1 = make_float4(xv.x + av.x, xv.y + av.y, xv.z + av.z, xv.w + av.w);
    }
    float s  = y0.x + y0.y + y0.z + y0.w + y1.x + y1.y + y1.z + y1.w;
    float sq = y0.x*y0.x + y0.y*y0.y + y0.z*y0.z + y0.w*y0.w
             + y1.x*y1.x + y1.y*y1.y + y1.z*y1.z + y1.w*y1.w;

#pragma unroll
    for (int off = 16; off; off >>= 1) {
        s  += __shfl_xor_sync(0xffffffffu, s,  off);
        sq += __shfl_xor_sync(0xffffffffu, sq, off);
    }
    __shared__ float shs[8], shq[8];
    __shared__ float stats[2];
    int w = tid >> 5, lane = tid & 31;
    if (lane == 0) { shs[w] = s; shq[w] = sq; }
    __syncthreads();
    if (tid == 0) {
        float ts = 0.f, tq = 0.f;
#pragma unroll
        for (int i = 0; i < 8; i++) { ts += shs[i]; tq += shq[i]; }
        float mu = ts / (float)DD;
        float var = tq / (float)DD - mu * mu;
        stats[0] = mu;
        stats[1] = rsqrtf(var + 1e-5f);
    }
    __syncthreads();
    float mu = stats[0], rinv = stats[1];

    const float4* g4 = (const float4*)gamma;
    const float4* b4 = (const float4*)beta;
    float4* lr = (float4*)(ln + (size_t)row * DD);
    {
        float4 gv = g4[tid], bv = b4[tid];
        float4 o = make_float4(gv.x * (y0.x - mu) * rinv + bv.x,
                               gv.y * (y0.y - mu) * rinv + bv.y,
                               gv.z * (y0.z - mu) * rinv + bv.z,
                               gv.w * (y0.w - mu) * rinv + bv.w);
        lr[tid] = o;
        gv = g4[tid + 256]; bv = b4[tid + 256];
        o = make_float4(gv.x * (y1.x - mu) * rinv + bv.x,
                        gv.y * (y1.y - mu) * rinv + bv.y,
                        gv.z * (y1.z - mu) * rinv + bv.z,
                        gv.w * (y1.w - mu) * rinv + bv.w);
        lr[tid + 256] = o;
    }
}

// ---------------------------------------------------------------------------
// Launch. Inputs: x, Wq, bq, Wk, bk, Wv, bv, Wo, bo, gamma, beta, num_heads.
// Output tuple (ln, attn_out, k, v) flattened into d_out.
// ---------------------------------------------------------------------------
extern "C" void kernel_launch(void* const* d_in, const int* in_sizes, int n_in,
                              void* d_out, int out_size)
{
    const float* x     = (const float*)d_in[0];
    const float* Wq    = (const float*)d_in[1];
    const float* bq    = (const float*)d_in[2];
    const float* Wk    = (const float*)d_in[3];
    const float* bk    = (const float*)d_in[4];
    const float* Wv    = (const float*)d_in[5];
    const float* bv    = (const float*)d_in[6];
    const float* Wo    = (const float*)d_in[7];
    const float* bo    = (const float*)d_in[8];
    const float* gamma = (const float*)d_in[9];
    const float* beta  = (const float*)d_in[10];

    float* out      = (float*)d_out;
    const size_t SEC = (size_t)BB * SS * DD;   // 8388608
    float* out_ln   = out;
    float* out_ao   = out + SEC;
    float* out_k    = out + 2 * SEC;
    float* out_v    = out + 3 * SEC;

    float *qptr = nullptr, *cptr = nullptr;
    uint32_t *xq = nullptr, *wq = nullptr, *kq = nullptr, *vq = nullptr, *cq = nullptr;
    cudaGetSymbolAddress((void**)&qptr, g_Q);
    cudaGetSymbolAddress((void**)&cptr, g_ctx);
    cudaGetSymbolAddress((void**)&xq,   g_xq);
    cudaGetSymbolAddress((void**)&wq,   g_wq);
    cudaGetSymbolAddress((void**)&kq,   g_kq);
    cudaGetSymbolAddress((void**)&vq,   g_vq);
    cudaGetSymbolAddress((void**)&cq,   g_cq);
    uint32_t* wqq = wq;
    uint32_t* wkq = wq + (size_t)DD * DD;
    uint32_t* wvq = wq + 2ull * DD * DD;
    uint32_t* woq = wq + 3ull * DD * DD;

    cudaFuncSetAttribute(attn_tc,
                         cudaFuncAttributeMaxDynamicSharedMemorySize, A2_SMEM_BYTES);
    cudaFuncSetAttribute(gemm_qkv,
                         cudaFuncAttributeMaxDynamicSharedMemorySize, TSMEM_BYTES);
    cudaFuncSetAttribute(gemm_o,
                         cudaFuncAttributeMaxDynamicSharedMemorySize, TSMEM_BYTES);

    // ---- one-shot pre-quantization of x + all 4 weights ----
    quant_all_kernel<<<QA_BLOCKS, 256>>>(
        (const float4*)x, (const float4*)Wq, (const float4*)Wk,
        (const float4*)Wv, (const float4*)Wo, (uint4*)xq, (uint4*)wq);

    // ---- merged Q/K/V projections (K/V also emit tf32 bits) ----
    dim3 qkvgrid(DD / TBN, MM / TBM, 3);   // (16, 32, 3)
    gemm_qkv<<<qkvgrid, 128, TSMEM_BYTES>>>(xq, wqq, wkq, wvq, bq, bk, bv,
                                            qptr, out_k, out_v, kq, vq);

    // ---- tensor-core flash attention (emits ctx fp32 + tf32 bits) ----
    dim3 agrid(SS / AQ, HH, BB);           // (16, 16, 2)
    attn_tc<<<agrid, 256, A2_SMEM_BYTES>>>(qptr, kq, vq, cptr, cq);

    // ---- output projection ----
    dim3 ogrid(DD / TBN, MM / TBM);        // (16, 32)
    gemm_o<<<ogrid, 128, TSMEM_BYTES>>>(cq, woq, bo, out_ao);

    // ---- residual + LayerNorm ----
    mhsa_add_ln_kernel<<<MM, 256>>>(x, out_ao, gamma, beta, out_ln);
}